// round 11
// baseline (speedup 1.0000x reference)
#include <cuda_runtime.h>
#include <cuda_bf16.h>
#include <cuda_fp16.h>
#include <cstdint>

#define C       256
#define N       4096
#define HEADS   4
#define HD      64
#define GROUPS  32
#define GSIZE   (C / GROUPS)
#define GELEMS  (GSIZE * N)
#define GN_EPS  1e-6f
// 0.125 * log2(e): softmax uses ex2 directly
#define QSCALE2 0.18033688011112042f
#define NSPLIT  2

typedef unsigned long long u64;

// bf16/f16 scratch. Channel (or key) index pair-permuted within 16-blocks
// ([0,1,8,9,2,3,10,11,4,5,12,13,6,7,14,15]) so MMA fragments are LDS.64.
__device__ __nv_bfloat16 g_hnb[N * C];     // groupnormed input [p][perm c]
__device__ __nv_bfloat16 g_wb [3 * C * C]; // weights bf16 [o][perm c]
__device__ __nv_bfloat16 g_qb [N * C];
__device__ __nv_bfloat16 g_kb [N * C];
__device__ __half        g_vtb[C * N];     // V transposed [c][perm p], f16
__device__ float g_po[NSPLIT * N * C];     // unnormalized O partials
__device__ float g_pl[NSPLIT * HEADS * N]; // l partials [split][head][p]
__device__ float g_linv[HEADS * N];        // 1/(l0+l1)

__device__ __forceinline__ int perm16(int i) {
    int b = i & ~15, l = i & 15, j = l >> 1, o = l & 1;
    int p = (j < 4) ? 4 * j : 4 * (j - 4) + 2;
    return b + p + o;
}
__device__ __forceinline__ int wpos8(int j) {
    return (j < 4) ? 2 * j : 2 * (j - 4) + 1;
}
__device__ __forceinline__ uint32_t pk_bf2(float lo, float hi) {
    uint32_t d;
    asm("cvt.rn.bf16x2.f32 %0, %1, %2;" : "=r"(d) : "f"(hi), "f"(lo));
    return d;
}
__device__ __forceinline__ uint32_t pkf16(float lo, float hi) {
    uint32_t d;
    asm("cvt.rn.f16x2.f32 %0, %1, %2;" : "=r"(d) : "f"(hi), "f"(lo));
    return d;
}
__device__ __forceinline__ uint32_t ex2h2(uint32_t x) {
    uint32_t r;
    asm("ex2.approx.f16x2 %0, %1;" : "=r"(r) : "r"(x));
    return r;
}
__device__ __forceinline__ void h2ff(uint32_t u, float& lo, float& hi) {
    asm("{.reg .f16 l, h;\n\t mov.b32 {l, h}, %2;\n\t"
        "cvt.f32.f16 %0, l;\n\t cvt.f32.f16 %1, h;}"
        : "=f"(lo), "=f"(hi) : "r"(u));
}
__device__ __forceinline__ void mma_bf16(float c[4],
        uint32_t a0, uint32_t a1, uint32_t a2, uint32_t a3,
        uint32_t b0, uint32_t b1) {
    asm volatile("mma.sync.aligned.m16n8k16.row.col.f32.bf16.bf16.f32 "
                 "{%0,%1,%2,%3}, {%4,%5,%6,%7}, {%8,%9}, {%0,%1,%2,%3};"
                 : "+f"(c[0]), "+f"(c[1]), "+f"(c[2]), "+f"(c[3])
                 : "r"(a0), "r"(a1), "r"(a2), "r"(a3), "r"(b0), "r"(b1));
}
__device__ __forceinline__ void mma_f16(float c[4],
        uint32_t a0, uint32_t a1, uint32_t a2, uint32_t a3,
        uint32_t b0, uint32_t b1) {
    asm volatile("mma.sync.aligned.m16n8k16.row.col.f32.f16.f16.f32 "
                 "{%0,%1,%2,%3}, {%4,%5,%6,%7}, {%8,%9}, {%0,%1,%2,%3};"
                 : "+f"(c[0]), "+f"(c[1]), "+f"(c[2]), "+f"(c[3])
                 : "r"(a0), "r"(a1), "r"(a2), "r"(a3), "r"(b0), "r"(b1));
}
__device__ __forceinline__ uint32_t smem_u32(const void* p) {
    uint32_t a;
    asm("{ .reg .u64 t; cvta.to.shared.u64 t, %1; cvt.u32.u64 %0, t; }"
        : "=r"(a) : "l"(p));
    return a;
}
__device__ __forceinline__ void cp16(uint32_t d, const void* s) {
    asm volatile("cp.async.cg.shared.global [%0], [%1], 16;" :: "r"(d), "l"(s));
}
#define CP_COMMIT() asm volatile("cp.async.commit_group;" ::: "memory")
#define CP_WAIT0()  asm volatile("cp.async.wait_group 0;" ::: "memory")
#define CP_WAIT1()  asm volatile("cp.async.wait_group 1;" ::: "memory")

__device__ __forceinline__ u64 fma2(u64 a, u64 b, u64 c) {
    u64 d;
    asm("fma.rn.f32x2 %0, %1, %2, %3;" : "=l"(d) : "l"(a), "l"(b), "l"(c));
    return d;
}
__device__ __forceinline__ u64 pk2(float lo, float hi) {
    u64 d;
    asm("mov.b64 %0, {%1, %2};" : "=l"(d) : "f"(lo), "f"(hi));
    return d;
}
__device__ __forceinline__ void upk2(u64 v, float& lo, float& hi) {
    asm("mov.b64 {%0, %1}, %2;" : "=f"(lo), "=f"(hi) : "l"(v));
}

// ---------------------------------------------------------------------------
// Kernel 1: GroupNorm stats + apply -> g_hnb bf16 [p][perm c] (validated).
// ---------------------------------------------------------------------------
__global__ void gn2_kernel(const float* __restrict__ x,
                           const float* __restrict__ gamma,
                           const float* __restrict__ beta) {
    const int b = blockIdx.x, tid = threadIdx.x;
    __shared__ float T[16 * 516];
    __shared__ float red[512];
    __shared__ float sc[16], sh[16], murs[4];

    for (int grp = 0; grp < 2; grp++) {
        const float4* xg = (const float4*)(x + (16 * b + 8 * grp) * N);
        float s = 0.f, s2 = 0.f;
        for (int i = tid; i < 8192; i += 256) {
            float4 v = xg[i];
            s  += (v.x + v.y) + (v.z + v.w);
            s2 += (v.x * v.x + v.y * v.y) + (v.z * v.z + v.w * v.w);
        }
        red[tid] = s; red[256 + tid] = s2;
        __syncthreads();
        for (int st = 128; st > 0; st >>= 1) {
            if (tid < st) { red[tid] += red[tid + st]; red[256 + tid] += red[256 + tid + st]; }
            __syncthreads();
        }
        if (tid == 0) {
            float mu = red[0] * (1.f / GELEMS);
            float var = red[256] * (1.f / GELEMS) - mu * mu;
            murs[grp] = mu; murs[2 + grp] = rsqrtf(var + GN_EPS);
        }
        __syncthreads();
    }
    if (tid < 16) {
        int grp = tid >> 3;
        float s = murs[2 + grp] * gamma[16 * b + tid];
        sc[tid] = s;
        sh[tid] = beta[16 * b + tid] - murs[grp] * s;
    }
    __syncthreads();

    uint32_t* hnw = (uint32_t*)g_hnb;
    for (int chunk = 0; chunk < 8; chunk++) {
        const int pc = chunk * 512;
        __syncthreads();
        for (int e = tid; e < 2048; e += 256) {
            int r = e >> 7, c4 = e & 127;
            *(float4*)(T + r * 516 + c4 * 4) =
                *(const float4*)(x + (16 * b + r) * N + pc + c4 * 4);
        }
        __syncthreads();
#pragma unroll
        for (int pp = 0; pp < 2; pp++) {
            const int pl = tid + pp * 256;
            float v[16];
#pragma unroll
            for (int c = 0; c < 16; c++)
                v[c] = fmaf(T[c * 516 + pl], sc[c], sh[c]);
            uint32_t wd[8];
#pragma unroll
            for (int j = 0; j < 8; j++)
                wd[wpos8(j)] = pk_bf2(v[2 * j], v[2 * j + 1]);
            uint4* dst = (uint4*)(hnw + (pc + pl) * 128 + b * 8);
            dst[0] = make_uint4(wd[0], wd[1], wd[2], wd[3]);
            dst[1] = make_uint4(wd[4], wd[5], wd[6], wd[7]);
        }
    }
}

// ---------------------------------------------------------------------------
// Kernel 1b: convert Wq/Wk/Wv to bf16 [o][perm c] (validated).
// ---------------------------------------------------------------------------
__global__ void wcvt_kernel(const float* __restrict__ Wq,
                            const float* __restrict__ Wk,
                            const float* __restrict__ Wv) {
    const int z = blockIdx.y;
    const float* W = (z == 0) ? Wq : (z == 1) ? Wk : Wv;
    uint32_t* wbw = (uint32_t*)g_wb + z * 32768;
    int e = blockIdx.x * 256 + threadIdx.x;
    int o = e >> 7, c2 = e & 127;
    float2 wv = *(const float2*)(W + o * 256 + 2 * c2);
    wbw[o * 128 + (c2 >> 3) * 8 + wpos8(c2 & 7)] = pk_bf2(wv.x, wv.y);
}

// ---------------------------------------------------------------------------
// Kernel 2: Q/K/V projection, bf16 mma (validated). V emitted as f16.
// ---------------------------------------------------------------------------
__global__ __launch_bounds__(256, 1) void qkv_mma_kernel(
        const float* __restrict__ bq, const float* __restrict__ bk,
        const float* __restrict__ bv) {
    __shared__ uint32_t sbuf[10240];
    uint32_t* Aw = sbuf;
    uint32_t* Bw = sbuf + 128 * 40;

    const int tid = threadIdx.x;
    const int w = tid >> 5, lane = tid & 31;
    const int g = lane >> 2, tig = lane & 3;
    const int p0 = blockIdx.x * 128;
    const int o0 = blockIdx.y * 128;
    const int z  = blockIdx.z;
    const float* bias = (z == 0) ? bq : (z == 1) ? bk : bv;

    const uint32_t* hnw = (const uint32_t*)g_hnb;
    const uint32_t* wbw = (const uint32_t*)g_wb + z * 32768;

    float acc[16][4] = {};

    for (int ch = 0; ch < 4; ch++) {
        __syncthreads();
#pragma unroll
        for (int i = 0; i < 4; i++) {
            int e = i * 256 + tid;
            int r = e >> 3, c4 = e & 7;
            *(uint4*)(Aw + r * 40 + c4 * 4) =
                *(const uint4*)(hnw + (p0 + r) * 128 + ch * 32 + c4 * 4);
            *(uint4*)(Bw + r * 40 + c4 * 4) =
                *(const uint4*)(wbw + (o0 + r) * 128 + ch * 32 + c4 * 4);
        }
        __syncthreads();

        uint32_t a[4][4];
#pragma unroll
        for (int ks = 0; ks < 4; ks++) {
            uint2 t0 = *(const uint2*)(Aw + (w * 16 + g)     * 40 + ks * 8 + 2 * tig);
            uint2 t1 = *(const uint2*)(Aw + (w * 16 + g + 8) * 40 + ks * 8 + 2 * tig);
            a[ks][0] = t0.x; a[ks][1] = t1.x; a[ks][2] = t0.y; a[ks][3] = t1.y;
        }
#pragma unroll
        for (int nt = 0; nt < 16; nt++) {
            const uint32_t* bb = Bw + (nt * 8 + g) * 40 + 2 * tig;
#pragma unroll
            for (int ks = 0; ks < 4; ks++) {
                uint2 t = *(const uint2*)(bb + ks * 8);
                mma_bf16(acc[nt], a[ks][0], a[ks][1], a[ks][2], a[ks][3], t.x, t.y);
            }
        }
    }

    if (z < 2) {
        const float s = (z == 0) ? QSCALE2 : 1.f;
        uint32_t* dst = (uint32_t*)((z == 0) ? g_qb : g_kb);
        const int p = p0 + w * 16 + g;
#pragma unroll
        for (int nt = 0; nt < 16; nt++) {
            const int o = o0 + nt * 8 + 2 * tig;
            const float b0 = bias[o], b1 = bias[o + 1];
            const int wi = (o0 >> 4) * 8 + (nt >> 1) * 8 + 2 * tig + (nt & 1);
            dst[p * 128 + wi]       = pk_bf2((acc[nt][0] + b0) * s, (acc[nt][1] + b1) * s);
            dst[(p + 8) * 128 + wi] = pk_bf2((acc[nt][2] + b0) * s, (acc[nt][3] + b1) * s);
        }
    } else {
        __syncthreads();
        __half* Vs = (__half*)sbuf;              // [o_local][perm p_local] pitch 130
        const int plA = perm16(w * 16 + g), plB = perm16(w * 16 + g + 8);
#pragma unroll
        for (int nt = 0; nt < 16; nt++) {
            const int ol = nt * 8 + 2 * tig;
            const float b0 = bias[o0 + ol], b1 = bias[o0 + ol + 1];
            Vs[ol * 130 + plA]       = __float2half(acc[nt][0] + b0);
            Vs[(ol + 1) * 130 + plA] = __float2half(acc[nt][1] + b1);
            Vs[ol * 130 + plB]       = __float2half(acc[nt][2] + b0);
            Vs[(ol + 1) * 130 + plB] = __float2half(acc[nt][3] + b1);
        }
        __syncthreads();
        uint32_t* vtw = (uint32_t*)g_vtb;
        const uint32_t* vsw = (const uint32_t*)Vs;
#pragma unroll
        for (int i = 0; i < 32; i++) {
            int e = i * 256 + tid;
            int r = e >> 6, cc = e & 63;
            vtw[(o0 + r) * 2048 + (p0 >> 1) + cc] = vsw[r * 65 + cc];
        }
    }
}

// ---------------------------------------------------------------------------
// Kernel 3: attention, split-K x2, in-register f16 P (ex2.approx.f16x2),
// f16 P.V mma, cp.async double buffering. Writes unnormalized partials.
// ---------------------------------------------------------------------------
#define PITCH 40
#define STG_W (2 * 64 * PITCH)
#define KT_PER (64 / NSPLIT)

__global__ __launch_bounds__(256, 2) void attn_mma_kernel() {
    __shared__ uint32_t buf[2 * STG_W];

    const int tid  = threadIdx.x;
    const int w    = tid >> 5, lane = tid & 31;
    const int g    = lane >> 2, tig = lane & 3;
    const int head = blockIdx.y;
    const int q0   = blockIdx.x * 128;
    const int spl  = blockIdx.z;
    const int kt0  = spl * KT_PER;

    const __nv_bfloat16* gq  = g_qb  + head * HD;
    const __nv_bfloat16* gk  = g_kb  + head * HD + kt0 * 64 * C;
    const __half*        gvt = g_vtb + head * HD * N + kt0 * 64;

    uint32_t qa[4][4];
    {
        const int r0 = q0 + w * 16 + g;
#pragma unroll
        for (int ks = 0; ks < 4; ks++) {
            uint2 t0 = *(const uint2*)(gq +  r0      * C + ks * 16 + 4 * tig);
            uint2 t1 = *(const uint2*)(gq + (r0 + 8) * C + ks * 16 + 4 * tig);
            qa[ks][0] = t0.x; qa[ks][1] = t1.x; qa[ks][2] = t0.y; qa[ks][3] = t1.y;
        }
    }

    const uint32_t sb = smem_u32(buf);
    int rr[2], cc4[2];
#pragma unroll
    for (int i = 0; i < 2; i++) {
        int e = i * 256 + tid;
        rr[i] = e >> 3; cc4[i] = e & 7;
    }

    float oacc[8][4] = {};
    float l0 = 0.f, l1 = 0.f;

#pragma unroll
    for (int i = 0; i < 2; i++) {
        cp16(sb + (rr[i] * PITCH + cc4[i] * 4) * 4, gk + rr[i] * C + cc4[i] * 8);
        cp16(sb + (64 * PITCH + rr[i] * PITCH + cc4[i] * 4) * 4,
             gvt + rr[i] * N + cc4[i] * 8);
    }
    CP_COMMIT();

    for (int kt = 0; kt < KT_PER; kt++) {
        const int cur = kt & 1;
        __syncthreads();
        if (kt + 1 < KT_PER) {
            const uint32_t db = sb + (cur ^ 1) * STG_W * 4;
            const __nv_bfloat16* ks_src = gk + (kt + 1) * 64 * C;
            const __half*        vs_src = gvt + (kt + 1) * 64;
#pragma unroll
            for (int i = 0; i < 2; i++) {
                cp16(db + (rr[i] * PITCH + cc4[i] * 4) * 4,
                     ks_src + rr[i] * C + cc4[i] * 8);
                cp16(db + (64 * PITCH + rr[i] * PITCH + cc4[i] * 4) * 4,
                     vs_src + rr[i] * N + cc4[i] * 8);
            }
            CP_COMMIT();
            CP_WAIT1();
        } else {
            CP_WAIT0();
        }
        __syncthreads();

        const uint32_t* Kc = buf + cur * STG_W;
        const uint32_t* Vc = Kc + 64 * PITCH;

        uint32_t p16[8][2];
#pragma unroll
        for (int nt = 0; nt < 8; nt++) {
            float s[4] = {};
            const uint32_t* kb = Kc + (nt * 8 + g) * PITCH + 2 * tig;
#pragma unroll
            for (int ks = 0; ks < 4; ks++) {
                uint2 b = *(const uint2*)(kb + ks * 8);
                mma_bf16(s, qa[ks][0], qa[ks][1], qa[ks][2], qa[ks][3], b.x, b.y);
            }
            p16[nt][0] = ex2h2(pkf16(s[0], s[1]));
            p16[nt][1] = ex2h2(pkf16(s[2], s[3]));
            float a0, a1, b0, b1;
            h2ff(p16[nt][0], a0, a1);
            h2ff(p16[nt][1], b0, b1);
            l0 += a0 + a1;
            l1 += b0 + b1;
        }

#pragma unroll
        for (int ks = 0; ks < 4; ks++) {
            const uint32_t pa0 = p16[2 * ks][0];
            const uint32_t pa1 = p16[2 * ks][1];
            const uint32_t pa2 = p16[2 * ks + 1][0];
            const uint32_t pa3 = p16[2 * ks + 1][1];
            const uint32_t* vb = Vc + g * PITCH + ks * 8 + 2 * tig;
#pragma unroll
            for (int nt = 0; nt < 8; nt++) {
                uint2 b = *(const uint2*)(vb + nt * 8 * PITCH);
                mma_f16(oacc[nt], pa0, pa1, pa2, pa3, b.x, b.y);
            }
        }
    }

    // ---- write partials (unnormalized) ----
    l0 += __shfl_xor_sync(0xffffffffu, l0, 1);
    l0 += __shfl_xor_sync(0xffffffffu, l0, 2);
    l1 += __shfl_xor_sync(0xffffffffu, l1, 1);
    l1 += __shfl_xor_sync(0xffffffffu, l1, 2);

    const int r0 = q0 + w * 16 + g;
    if (tig == 0) {
        g_pl[(spl * HEADS + head) * N + r0]     = l0;
        g_pl[(spl * HEADS + head) * N + r0 + 8] = l1;
    }
    float* po = g_po + spl * N * C;
#pragma unroll
    for (int nt = 0; nt < 8; nt++) {
        const int col = head * HD + nt * 8 + 2 * tig;
        *(float2*)(po + r0 * C + col)       = make_float2(oacc[nt][0], oacc[nt][1]);
        *(float2*)(po + (r0 + 8) * C + col) = make_float2(oacc[nt][2], oacc[nt][3]);
    }
}

// ---------------------------------------------------------------------------
// Kernel 3b: inverse of combined l. 16384 elements.
// ---------------------------------------------------------------------------
__global__ void linv_kernel() {
    const int i = blockIdx.x * 256 + threadIdx.x;
    g_linv[i] = 1.f / (g_pl[i] + g_pl[HEADS * N + i]);
}

// ---------------------------------------------------------------------------
// Kernel 4: output projection + residual, f32x2 packed, split-K combine fused
// into the B-tile load. OUT[o][p] = x + bp[o] + sum_c Wp[o][c]*Gn[c][p],
// Gn[c][p] = (po0[f]+po1[f])*linv, f = c*4096+p (flat reinterpretation).
// ---------------------------------------------------------------------------
__global__ __launch_bounds__(256, 2) void proj2_kernel(
        const float* __restrict__ Wp, const float* __restrict__ bp,
        const float* __restrict__ x,  float* __restrict__ out) {
    const int p0 = blockIdx.x * 64;
    const int o0 = blockIdx.y * 64;
    const int tid = threadIdx.x;
    const int tx = tid & 15, ty = tid >> 4;

    __shared__ u64   Wsd[32 * 66];   // [cc][o] duplicated pairs
    __shared__ float Ms [32 * 64];   // [cc][p] normalized

    const int h    = (p0 >> 6) & 3;
    const int pixb = p0 >> 8;
    const float* po0 = g_po;
    const float* po1 = g_po + N * C;

    u64 acc[4][2] = {};

    for (int c0 = 0; c0 < C; c0 += 32) {
        __syncthreads();
#pragma unroll
        for (int i = 0; i < 8; i++) {
            int e = tid + i * 256;
            int cc = e & 31, o = e >> 5;
            float wv = Wp[(o0 + o) * C + c0 + cc];
            Wsd[cc * 66 + o] = pk2(wv, wv);
        }
#pragma unroll
        for (int i = 0; i < 8; i++) {
            int e = tid + i * 256;
            int r = e >> 6, cc = e & 63;
            int f = (c0 + r) * N + p0 + cc;
            float li = g_linv[h * N + (c0 + r) * 16 + pixb];
            Ms[r * 64 + cc] = (po0[f] + po1[f]) * li;
        }
        __syncthreads();
#pragma unroll
        for (int cc = 0; cc < 32; cc++) {
            ulonglong2 aA = *(const ulonglong2*)(Wsd + cc * 66 + ty * 4);
            ulonglong2 aB = *(const ulonglong2*)(Wsd + cc * 66 + ty * 4 + 2);
            ulonglong2 bb = *(const ulonglong2*)(Ms + cc * 64 + tx * 4);
            acc[0][0] = fma2(aA.x, bb.x, acc[0][0]);
            acc[0][1] = fma2(aA.x, bb.y, acc[0][1]);
            acc[1][0] = fma2(aA.y, bb.x, acc[1][0]);
            acc[1][1] = fma2(aA.y, bb.y, acc[1][1]);
            acc[2][0] = fma2(aB.x, bb.x, acc[2][0]);
            acc[2][1] = fma2(aB.x, bb.y, acc[2][1]);
            acc[3][0] = fma2(aB.y, bb.x, acc[3][0]);
            acc[3][1] = fma2(aB.y, bb.y, acc[3][1]);
        }
    }

#pragma unroll
    for (int i = 0; i < 4; i++) {
        const int oo = o0 + ty * 4 + i;
        const float bbv = bp[oo];
        float a0, a1, a2, a3;
        upk2(acc[i][0], a0, a1);
        upk2(acc[i][1], a2, a3);
        const int pp = p0 + tx * 4;
        float4 xv = *(const float4*)(x + oo * N + pp);
        *(float4*)(out + oo * N + pp) =
            make_float4(xv.x + bbv + a0, xv.y + bbv + a1,
                        xv.z + bbv + a2, xv.w + bbv + a3);
    }
}

// ---------------------------------------------------------------------------
extern "C" void kernel_launch(void* const* d_in, const int* in_sizes, int n_in,
                              void* d_out, int out_size) {
    const float* x     = (const float*)d_in[0];
    const float* gamma = (const float*)d_in[1];
    const float* beta  = (const float*)d_in[2];
    const float* Wq    = (const float*)d_in[3];
    const float* bq    = (const float*)d_in[4];
    const float* Wk    = (const float*)d_in[5];
    const float* bk    = (const float*)d_in[6];
    const float* Wv    = (const float*)d_in[7];
    const float* bv    = (const float*)d_in[8];
    const float* Wp    = (const float*)d_in[9];
    const float* bp    = (const float*)d_in[10];
    float* out = (float*)d_out;

    gn2_kernel<<<16, 256>>>(x, gamma, beta);

    dim3 gw(128, 3);
    wcvt_kernel<<<gw, 256>>>(Wq, Wk, Wv);

    dim3 g2(N / 128, C / 128, 3);
    qkv_mma_kernel<<<g2, 256>>>(bq, bk, bv);

    dim3 g3(N / 128, HEADS, NSPLIT);
    attn_mma_kernel<<<g3, 256>>>();

    linv_kernel<<<HEADS * N / 256, 256>>>();

    dim3 g4(N / 64, C / 64);
    proj2_kernel<<<g4, 256>>>(Wp, bp, x, out);
}

// round 12
// speedup vs baseline: 1.0171x; 1.0171x over previous
#include <cuda_runtime.h>
#include <cuda_bf16.h>
#include <cstdint>

#define C       256
#define N       4096
#define HEADS   4
#define HD      64
#define GROUPS  32
#define GSIZE   (C / GROUPS)
#define GELEMS  (GSIZE * N)
#define GN_EPS  1e-6f
// 0.125 * log2(e): softmax uses ex2 directly
#define QSCALE2 0.18033688011112042f
#define NSPLIT  2

// bf16 scratch. Channel (or key) index pair-permuted within 16-blocks
// ([0,1,8,9,2,3,10,11,4,5,12,13,6,7,14,15]) so MMA fragments are LDS.64.
__device__ __nv_bfloat16 g_hnb[N * C];     // groupnormed input [p][perm c]
__device__ __nv_bfloat16 g_wb [3 * C * C]; // weights bf16 [o][perm c]
__device__ __nv_bfloat16 g_qb [N * C];
__device__ __nv_bfloat16 g_kb [N * C];
__device__ __nv_bfloat16 g_vtb[C * N];     // V transposed [c][perm p]
__device__ float g_po[NSPLIT * N * C];     // unnormalized O partials
__device__ float g_pl[NSPLIT * HEADS * N]; // l partials [split][head][p]
__device__ float g_o [N * C];              // combined attention output

__device__ __forceinline__ int perm16(int i) {
    int b = i & ~15, l = i & 15, j = l >> 1, o = l & 1;
    int p = (j < 4) ? 4 * j : 4 * (j - 4) + 2;
    return b + p + o;
}
__device__ __forceinline__ int wpos8(int j) {
    return (j < 4) ? 2 * j : 2 * (j - 4) + 1;
}
__device__ __forceinline__ uint32_t pk_bf2(float lo, float hi) {
    uint32_t d;
    asm("cvt.rn.bf16x2.f32 %0, %1, %2;" : "=r"(d) : "f"(hi), "f"(lo));
    return d;
}
__device__ __forceinline__ float ex2(float x) {
    float r;
    asm("ex2.approx.f32 %0, %1;" : "=f"(r) : "f"(x));
    return r;
}
__device__ __forceinline__ void mma_bf16(float c[4],
        uint32_t a0, uint32_t a1, uint32_t a2, uint32_t a3,
        uint32_t b0, uint32_t b1) {
    asm volatile("mma.sync.aligned.m16n8k16.row.col.f32.bf16.bf16.f32 "
                 "{%0,%1,%2,%3}, {%4,%5,%6,%7}, {%8,%9}, {%0,%1,%2,%3};"
                 : "+f"(c[0]), "+f"(c[1]), "+f"(c[2]), "+f"(c[3])
                 : "r"(a0), "r"(a1), "r"(a2), "r"(a3), "r"(b0), "r"(b1));
}
__device__ __forceinline__ uint32_t smem_u32(const void* p) {
    uint32_t a;
    asm("{ .reg .u64 t; cvta.to.shared.u64 t, %1; cvt.u32.u64 %0, t; }"
        : "=r"(a) : "l"(p));
    return a;
}
__device__ __forceinline__ void cp16(uint32_t d, const void* s) {
    asm volatile("cp.async.cg.shared.global [%0], [%1], 16;" :: "r"(d), "l"(s));
}
#define CP_COMMIT() asm volatile("cp.async.commit_group;" ::: "memory")
#define CP_WAIT0()  asm volatile("cp.async.wait_group 0;" ::: "memory")
#define CP_WAIT1()  asm volatile("cp.async.wait_group 1;" ::: "memory")

// ---------------------------------------------------------------------------
// Kernel 1: GroupNorm stats + apply -> g_hnb bf16 [p][perm c] (validated).
// ---------------------------------------------------------------------------
__global__ void gn2_kernel(const float* __restrict__ x,
                           const float* __restrict__ gamma,
                           const float* __restrict__ beta) {
    const int b = blockIdx.x, tid = threadIdx.x;
    __shared__ float T[16 * 516];
    __shared__ float red[512];
    __shared__ float sc[16], sh[16], murs[4];

    for (int grp = 0; grp < 2; grp++) {
        const float4* xg = (const float4*)(x + (16 * b + 8 * grp) * N);
        float s = 0.f, s2 = 0.f;
        for (int i = tid; i < 8192; i += 256) {
            float4 v = xg[i];
            s  += (v.x + v.y) + (v.z + v.w);
            s2 += (v.x * v.x + v.y * v.y) + (v.z * v.z + v.w * v.w);
        }
        red[tid] = s; red[256 + tid] = s2;
        __syncthreads();
        for (int st = 128; st > 0; st >>= 1) {
            if (tid < st) { red[tid] += red[tid + st]; red[256 + tid] += red[256 + tid + st]; }
            __syncthreads();
        }
        if (tid == 0) {
            float mu = red[0] * (1.f / GELEMS);
            float var = red[256] * (1.f / GELEMS) - mu * mu;
            murs[grp] = mu; murs[2 + grp] = rsqrtf(var + GN_EPS);
        }
        __syncthreads();
    }
    if (tid < 16) {
        int grp = tid >> 3;
        float s = murs[2 + grp] * gamma[16 * b + tid];
        sc[tid] = s;
        sh[tid] = beta[16 * b + tid] - murs[grp] * s;
    }
    __syncthreads();

    uint32_t* hnw = (uint32_t*)g_hnb;
    for (int chunk = 0; chunk < 8; chunk++) {
        const int pc = chunk * 512;
        __syncthreads();
        for (int e = tid; e < 2048; e += 256) {
            int r = e >> 7, c4 = e & 127;
            *(float4*)(T + r * 516 + c4 * 4) =
                *(const float4*)(x + (16 * b + r) * N + pc + c4 * 4);
        }
        __syncthreads();
#pragma unroll
        for (int pp = 0; pp < 2; pp++) {
            const int pl = tid + pp * 256;
            float v[16];
#pragma unroll
            for (int c = 0; c < 16; c++)
                v[c] = fmaf(T[c * 516 + pl], sc[c], sh[c]);
            uint32_t wd[8];
#pragma unroll
            for (int j = 0; j < 8; j++)
                wd[wpos8(j)] = pk_bf2(v[2 * j], v[2 * j + 1]);
            uint4* dst = (uint4*)(hnw + (pc + pl) * 128 + b * 8);
            dst[0] = make_uint4(wd[0], wd[1], wd[2], wd[3]);
            dst[1] = make_uint4(wd[4], wd[5], wd[6], wd[7]);
        }
    }
}

// ---------------------------------------------------------------------------
// Kernel 1b: convert Wq/Wk/Wv to bf16 [o][perm c] (validated).
// ---------------------------------------------------------------------------
__global__ void wcvt_kernel(const float* __restrict__ Wq,
                            const float* __restrict__ Wk,
                            const float* __restrict__ Wv) {
    const int z = blockIdx.y;
    const float* W = (z == 0) ? Wq : (z == 1) ? Wk : Wv;
    uint32_t* wbw = (uint32_t*)g_wb + z * 32768;
    int e = blockIdx.x * 256 + threadIdx.x;
    int o = e >> 7, c2 = e & 127;
    float2 wv = *(const float2*)(W + o * 256 + 2 * c2);
    wbw[o * 128 + (c2 >> 3) * 8 + wpos8(c2 & 7)] = pk_bf2(wv.x, wv.y);
}

// ---------------------------------------------------------------------------
// Kernel 2: Q/K/V projection, bf16 mma (validated r8-r10).
// ---------------------------------------------------------------------------
__global__ __launch_bounds__(256, 1) void qkv_mma_kernel(
        const float* __restrict__ bq, const float* __restrict__ bk,
        const float* __restrict__ bv) {
    __shared__ uint32_t sbuf[10240];
    uint32_t* Aw = sbuf;
    uint32_t* Bw = sbuf + 128 * 40;

    const int tid = threadIdx.x;
    const int w = tid >> 5, lane = tid & 31;
    const int g = lane >> 2, tig = lane & 3;
    const int p0 = blockIdx.x * 128;
    const int o0 = blockIdx.y * 128;
    const int z  = blockIdx.z;
    const float* bias = (z == 0) ? bq : (z == 1) ? bk : bv;

    const uint32_t* hnw = (const uint32_t*)g_hnb;
    const uint32_t* wbw = (const uint32_t*)g_wb + z * 32768;

    float acc[16][4] = {};

    for (int ch = 0; ch < 4; ch++) {
        __syncthreads();
#pragma unroll
        for (int i = 0; i < 4; i++) {
            int e = i * 256 + tid;
            int r = e >> 3, c4 = e & 7;
            *(uint4*)(Aw + r * 40 + c4 * 4) =
                *(const uint4*)(hnw + (p0 + r) * 128 + ch * 32 + c4 * 4);
            *(uint4*)(Bw + r * 40 + c4 * 4) =
                *(const uint4*)(wbw + (o0 + r) * 128 + ch * 32 + c4 * 4);
        }
        __syncthreads();

        uint32_t a[4][4];
#pragma unroll
        for (int ks = 0; ks < 4; ks++) {
            uint2 t0 = *(const uint2*)(Aw + (w * 16 + g)     * 40 + ks * 8 + 2 * tig);
            uint2 t1 = *(const uint2*)(Aw + (w * 16 + g + 8) * 40 + ks * 8 + 2 * tig);
            a[ks][0] = t0.x; a[ks][1] = t1.x; a[ks][2] = t0.y; a[ks][3] = t1.y;
        }
#pragma unroll
        for (int nt = 0; nt < 16; nt++) {
            const uint32_t* bb = Bw + (nt * 8 + g) * 40 + 2 * tig;
#pragma unroll
            for (int ks = 0; ks < 4; ks++) {
                uint2 t = *(const uint2*)(bb + ks * 8);
                mma_bf16(acc[nt], a[ks][0], a[ks][1], a[ks][2], a[ks][3], t.x, t.y);
            }
        }
    }

    if (z < 2) {
        const float s = (z == 0) ? QSCALE2 : 1.f;
        uint32_t* dst = (uint32_t*)((z == 0) ? g_qb : g_kb);
        const int p = p0 + w * 16 + g;
#pragma unroll
        for (int nt = 0; nt < 16; nt++) {
            const int o = o0 + nt * 8 + 2 * tig;
            const float b0 = bias[o], b1 = bias[o + 1];
            const int wi = (o0 >> 4) * 8 + (nt >> 1) * 8 + 2 * tig + (nt & 1);
            dst[p * 128 + wi]       = pk_bf2((acc[nt][0] + b0) * s, (acc[nt][1] + b1) * s);
            dst[(p + 8) * 128 + wi] = pk_bf2((acc[nt][2] + b0) * s, (acc[nt][3] + b1) * s);
        }
    } else {
        __syncthreads();
        __nv_bfloat16* Vs = (__nv_bfloat16*)sbuf;
        const int plA = perm16(w * 16 + g), plB = perm16(w * 16 + g + 8);
#pragma unroll
        for (int nt = 0; nt < 16; nt++) {
            const int ol = nt * 8 + 2 * tig;
            const float b0 = bias[o0 + ol], b1 = bias[o0 + ol + 1];
            Vs[ol * 130 + plA]       = __float2bfloat16(acc[nt][0] + b0);
            Vs[(ol + 1) * 130 + plA] = __float2bfloat16(acc[nt][1] + b1);
            Vs[ol * 130 + plB]       = __float2bfloat16(acc[nt][2] + b0);
            Vs[(ol + 1) * 130 + plB] = __float2bfloat16(acc[nt][3] + b1);
        }
        __syncthreads();
        uint32_t* vtw = (uint32_t*)g_vtb;
        const uint32_t* vsw = (const uint32_t*)Vs;
#pragma unroll
        for (int i = 0; i < 32; i++) {
            int e = i * 256 + tid;
            int r = e >> 6, cc = e & 63;
            vtw[(o0 + r) * 2048 + (p0 >> 1) + cc] = vsw[r * 65 + cc];
        }
    }
}

// ---------------------------------------------------------------------------
// Kernel 3: attention, split-K x2, interleaved S/exp/PV per key-chunk,
// dual S-accumulator chains, in-register bf16 P, cp.async double buffering.
// ---------------------------------------------------------------------------
#define PITCH 40
#define STG_W (2 * 64 * PITCH)
#define KT_PER (64 / NSPLIT)

__global__ __launch_bounds__(256, 2) void attn_mma_kernel() {
    __shared__ uint32_t buf[2 * STG_W];

    const int tid  = threadIdx.x;
    const int w    = tid >> 5, lane = tid & 31;
    const int g    = lane >> 2, tig = lane & 3;
    const int head = blockIdx.y;
    const int q0   = blockIdx.x * 128;
    const int spl  = blockIdx.z;
    const int kt0  = spl * KT_PER;

    const __nv_bfloat16* gq  = g_qb  + head * HD;
    const __nv_bfloat16* gk  = g_kb  + head * HD + kt0 * 64 * C;
    const __nv_bfloat16* gvt = g_vtb + head * HD * N + kt0 * 64;

    uint32_t qa[4][4];
    {
        const int r0 = q0 + w * 16 + g;
#pragma unroll
        for (int ks = 0; ks < 4; ks++) {
            uint2 t0 = *(const uint2*)(gq +  r0      * C + ks * 16 + 4 * tig);
            uint2 t1 = *(const uint2*)(gq + (r0 + 8) * C + ks * 16 + 4 * tig);
            qa[ks][0] = t0.x; qa[ks][1] = t1.x; qa[ks][2] = t0.y; qa[ks][3] = t1.y;
        }
    }

    const uint32_t sb = smem_u32(buf);
    int rr[2], cc4[2];
#pragma unroll
    for (int i = 0; i < 2; i++) {
        int e = i * 256 + tid;
        rr[i] = e >> 3; cc4[i] = e & 7;
    }

    float oacc[8][4] = {};
    float l0 = 0.f, l1 = 0.f;

#pragma unroll
    for (int i = 0; i < 2; i++) {
        cp16(sb + (rr[i] * PITCH + cc4[i] * 4) * 4, gk + rr[i] * C + cc4[i] * 8);
        cp16(sb + (64 * PITCH + rr[i] * PITCH + cc4[i] * 4) * 4,
             gvt + rr[i] * N + cc4[i] * 8);
    }
    CP_COMMIT();

    for (int kt = 0; kt < KT_PER; kt++) {
        const int cur = kt & 1;
        __syncthreads();
        if (kt + 1 < KT_PER) {
            const uint32_t db = sb + (cur ^ 1) * STG_W * 4;
            const __nv_bfloat16* ks_src = gk + (kt + 1) * 64 * C;
            const __nv_bfloat16* vs_src = gvt + (kt + 1) * 64;
#pragma unroll
            for (int i = 0; i < 2; i++) {
                cp16(db + (rr[i] * PITCH + cc4[i] * 4) * 4,
                     ks_src + rr[i] * C + cc4[i] * 8);
                cp16(db + (64 * PITCH + rr[i] * PITCH + cc4[i] * 4) * 4,
                     vs_src + rr[i] * N + cc4[i] * 8);
            }
            CP_COMMIT();
            CP_WAIT1();
        } else {
            CP_WAIT0();
        }
        __syncthreads();

        const uint32_t* Kc = buf + cur * STG_W;
        const uint32_t* Vc = Kc + 64 * PITCH;

        // interleaved: per key-chunk ksv, compute 2 S n-tiles, exp, then the
        // 8 independent PV MMAs for that chunk (ptxas overlaps exp with S of
        // the next chunk; PV chain depth on oacc is 1 per chunk).
#pragma unroll
        for (int ksv = 0; ksv < 4; ksv++) {
            float p[2][4];
#pragma unroll
            for (int j = 0; j < 2; j++) {
                const int nt = 2 * ksv + j;
                float sA[4] = {}, sB[4] = {};
                const uint32_t* kb = Kc + (nt * 8 + g) * PITCH + 2 * tig;
                uint2 b0 = *(const uint2*)(kb);
                uint2 b1 = *(const uint2*)(kb + 8);
                uint2 b2 = *(const uint2*)(kb + 16);
                uint2 b3 = *(const uint2*)(kb + 24);
                mma_bf16(sA, qa[0][0], qa[0][1], qa[0][2], qa[0][3], b0.x, b0.y);
                mma_bf16(sB, qa[1][0], qa[1][1], qa[1][2], qa[1][3], b1.x, b1.y);
                mma_bf16(sA, qa[2][0], qa[2][1], qa[2][2], qa[2][3], b2.x, b2.y);
                mma_bf16(sB, qa[3][0], qa[3][1], qa[3][2], qa[3][3], b3.x, b3.y);
                p[j][0] = ex2(sA[0] + sB[0]);
                p[j][1] = ex2(sA[1] + sB[1]);
                p[j][2] = ex2(sA[2] + sB[2]);
                p[j][3] = ex2(sA[3] + sB[3]);
            }
            l0 += (p[0][0] + p[0][1]) + (p[1][0] + p[1][1]);
            l1 += (p[0][2] + p[0][3]) + (p[1][2] + p[1][3]);

            const uint32_t pa0 = pk_bf2(p[0][0], p[0][1]);
            const uint32_t pa1 = pk_bf2(p[0][2], p[0][3]);
            const uint32_t pa2 = pk_bf2(p[1][0], p[1][1]);
            const uint32_t pa3 = pk_bf2(p[1][2], p[1][3]);
            const uint32_t* vb = Vc + g * PITCH + ksv * 8 + 2 * tig;
#pragma unroll
            for (int nt = 0; nt < 8; nt++) {
                uint2 b = *(const uint2*)(vb + nt * 8 * PITCH);
                mma_bf16(oacc[nt], pa0, pa1, pa2, pa3, b.x, b.y);
            }
        }
    }

    // ---- write partials (unnormalized) ----
    l0 += __shfl_xor_sync(0xffffffffu, l0, 1);
    l0 += __shfl_xor_sync(0xffffffffu, l0, 2);
    l1 += __shfl_xor_sync(0xffffffffu, l1, 1);
    l1 += __shfl_xor_sync(0xffffffffu, l1, 2);

    const int r0 = q0 + w * 16 + g;
    if (tig == 0) {
        g_pl[(spl * HEADS + head) * N + r0]     = l0;
        g_pl[(spl * HEADS + head) * N + r0 + 8] = l1;
    }
    float* po = g_po + spl * N * C;
#pragma unroll
    for (int nt = 0; nt < 8; nt++) {
        const int col = head * HD + nt * 8 + 2 * tig;
        *(float2*)(po + r0 * C + col)       = make_float2(oacc[nt][0], oacc[nt][1]);
        *(float2*)(po + (r0 + 8) * C + col) = make_float2(oacc[nt][2], oacc[nt][3]);
    }
}

// ---------------------------------------------------------------------------
// Kernel 3b: combine split-K partials -> g_o (validated r10).
// ---------------------------------------------------------------------------
__global__ void combine_kernel() {
    const int idx = blockIdx.x * 256 + threadIdx.x;   // float4 index
    const int p  = idx >> 6;
    const int c4 = idx & 63;
    const int h  = c4 >> 4;
    const float l = g_pl[h * N + p] + g_pl[(HEADS + h) * N + p];
    const float inv = 1.f / l;
    float4 a = ((const float4*)g_po)[idx];
    float4 b = ((const float4*)(g_po + N * C))[idx];
    ((float4*)g_o)[idx] = make_float4((a.x + b.x) * inv, (a.y + b.y) * inv,
                                      (a.z + b.z) * inv, (a.w + b.w) * inv);
}

// ---------------------------------------------------------------------------
// Kernel 4: output projection + residual (fp32, validated).
// ---------------------------------------------------------------------------
__global__ void proj_kernel(const float* __restrict__ Wp, const float* __restrict__ bp,
                            const float* __restrict__ x,  float* __restrict__ out) {
    const int p0 = blockIdx.x * 64;
    const int o0 = blockIdx.y * 64;
    const int tid = threadIdx.x;
    const int tx = tid & 15, ty = tid >> 4;

    __shared__ float Ws[64][33];
    __shared__ float Ms[32][64];

    float acc[4][4] = {};
    for (int c0 = 0; c0 < C; c0 += 32) {
        __syncthreads();
#pragma unroll
        for (int i = 0; i < 8; i++) {
            int idx = tid + i * 256;
            int r = idx >> 5, cc = idx & 31;
            Ws[r][cc] = Wp[(o0 + r) * C + c0 + cc];
        }
#pragma unroll
        for (int i = 0; i < 8; i++) {
            int idx = tid + i * 256;
            int r = idx >> 6, cc = idx & 63;
            Ms[r][cc] = g_o[(c0 + r) * N + p0 + cc];
        }
        __syncthreads();
#pragma unroll
        for (int cc = 0; cc < 32; cc++) {
            float a[4], b[4];
#pragma unroll
            for (int k = 0; k < 4; k++) a[k] = Ws[ty * 4 + k][cc];
#pragma unroll
            for (int k = 0; k < 4; k++) b[k] = Ms[cc][tx * 4 + k];
#pragma unroll
            for (int i = 0; i < 4; i++)
#pragma unroll
                for (int j = 0; j < 4; j++)
                    acc[i][j] = fmaf(a[i], b[j], acc[i][j]);
        }
    }
#pragma unroll
    for (int i = 0; i < 4; i++) {
        const int oo = o0 + ty * 4 + i;
        const float bb = bp[oo];
#pragma unroll
        for (int j = 0; j < 4; j++) {
            const int pp = p0 + tx * 4 + j;
            out[oo * N + pp] = x[oo * N + pp] + bb + acc[i][j];
        }
    }
}

// ---------------------------------------------------------------------------
extern "C" void kernel_launch(void* const* d_in, const int* in_sizes, int n_in,
                              void* d_out, int out_size) {
    const float* x     = (const float*)d_in[0];
    const float* gamma = (const float*)d_in[1];
    const float* beta  = (const float*)d_in[2];
    const float* Wq    = (const float*)d_in[3];
    const float* bq    = (const float*)d_in[4];
    const float* Wk    = (const float*)d_in[5];
    const float* bk    = (const float*)d_in[6];
    const float* Wv    = (const float*)d_in[7];
    const float* bv    = (const float*)d_in[8];
    const float* Wp    = (const float*)d_in[9];
    const float* bp    = (const float*)d_in[10];
    float* out = (float*)d_out;

    gn2_kernel<<<16, 256>>>(x, gamma, beta);

    dim3 gw(128, 3);
    wcvt_kernel<<<gw, 256>>>(Wq, Wk, Wv);

    dim3 g2(N / 128, C / 128, 3);
    qkv_mma_kernel<<<g2, 256>>>(bq, bk, bv);

    dim3 g3(N / 128, HEADS, NSPLIT);
    attn_mma_kernel<<<g3, 256>>>();

    combine_kernel<<<1024, 256>>>();

    dim3 g4(N / 64, C / 64);
    proj_kernel<<<g4, 256>>>(Wp, bp, x, out);
}

// round 13
// speedup vs baseline: 1.1151x; 1.0963x over previous
#include <cuda_runtime.h>
#include <cuda_bf16.h>
#include <cstdint>

#define C       256
#define N       4096
#define HEADS   4
#define HD      64
#define GROUPS  32
#define GSIZE   (C / GROUPS)
#define GELEMS  (GSIZE * N)
#define GN_EPS  1e-6f
// 0.125 * log2(e): softmax uses ex2 directly
#define QSCALE2 0.18033688011112042f
#define NSPLIT  2

// bf16 scratch. Channel (or key) index pair-permuted within 16-blocks
// ([0,1,8,9,2,3,10,11,4,5,12,13,6,7,14,15]) so MMA fragments are LDS.64.
__device__ __nv_bfloat16 g_hnb[N * C];     // groupnormed input [p][perm c]
__device__ __nv_bfloat16 g_wb [3 * C * C]; // weights bf16 [o][perm c]
__device__ __nv_bfloat16 g_qb [N * C];
__device__ __nv_bfloat16 g_kb [N * C];
__device__ __nv_bfloat16 g_vtb[C * N];     // V transposed [c][perm p]
__device__ float g_po[NSPLIT * N * C];     // unnormalized O partials
__device__ float g_pl[NSPLIT * HEADS * N]; // l partials [split][head][p]
__device__ float g_linv[HEADS * N];        // 1/(l0+l1)
__device__ float g_ot [N * C];             // proj B operand [p2][perm8 c], tf32
__device__ float g_wpt[C * C];             // Wp tf32 [o][perm8 c]

__device__ __forceinline__ int perm16(int i) {
    int b = i & ~15, l = i & 15, j = l >> 1, o = l & 1;
    int p = (j < 4) ? 4 * j : 4 * (j - 4) + 2;
    return b + p + o;
}
__device__ __forceinline__ int wpos8(int j) {
    return (j < 4) ? 2 * j : 2 * (j - 4) + 1;
}
__device__ __forceinline__ uint32_t pk_bf2(float lo, float hi) {
    uint32_t d;
    asm("cvt.rn.bf16x2.f32 %0, %1, %2;" : "=r"(d) : "f"(hi), "f"(lo));
    return d;
}
__device__ __forceinline__ float ex2(float x) {
    float r;
    asm("ex2.approx.f32 %0, %1;" : "=f"(r) : "f"(x));
    return r;
}
__device__ __forceinline__ float tf32r(float f) {
    uint32_t u;
    asm("cvt.rna.tf32.f32 %0, %1;" : "=r"(u) : "f"(f));
    return __uint_as_float(u);
}
__device__ __forceinline__ void mma_bf16(float c[4],
        uint32_t a0, uint32_t a1, uint32_t a2, uint32_t a3,
        uint32_t b0, uint32_t b1) {
    asm volatile("mma.sync.aligned.m16n8k16.row.col.f32.bf16.bf16.f32 "
                 "{%0,%1,%2,%3}, {%4,%5,%6,%7}, {%8,%9}, {%0,%1,%2,%3};"
                 : "+f"(c[0]), "+f"(c[1]), "+f"(c[2]), "+f"(c[3])
                 : "r"(a0), "r"(a1), "r"(a2), "r"(a3), "r"(b0), "r"(b1));
}
__device__ __forceinline__ void mma_tf32(float c[4],
        uint32_t a0, uint32_t a1, uint32_t a2, uint32_t a3,
        uint32_t b0, uint32_t b1) {
    asm volatile("mma.sync.aligned.m16n8k8.row.col.f32.tf32.tf32.f32 "
                 "{%0,%1,%2,%3}, {%4,%5,%6,%7}, {%8,%9}, {%0,%1,%2,%3};"
                 : "+f"(c[0]), "+f"(c[1]), "+f"(c[2]), "+f"(c[3])
                 : "r"(a0), "r"(a1), "r"(a2), "r"(a3), "r"(b0), "r"(b1));
}
__device__ __forceinline__ uint32_t smem_u32(const void* p) {
    uint32_t a;
    asm("{ .reg .u64 t; cvta.to.shared.u64 t, %1; cvt.u32.u64 %0, t; }"
        : "=r"(a) : "l"(p));
    return a;
}
__device__ __forceinline__ void cp16(uint32_t d, const void* s) {
    asm volatile("cp.async.cg.shared.global [%0], [%1], 16;" :: "r"(d), "l"(s));
}
#define CP_COMMIT() asm volatile("cp.async.commit_group;" ::: "memory")
#define CP_WAIT0()  asm volatile("cp.async.wait_group 0;" ::: "memory")
#define CP_WAIT1()  asm volatile("cp.async.wait_group 1;" ::: "memory")

// ---------------------------------------------------------------------------
// Kernel 1: GroupNorm stats + apply -> g_hnb bf16 [p][perm c] (validated).
// ---------------------------------------------------------------------------
__global__ void gn2_kernel(const float* __restrict__ x,
                           const float* __restrict__ gamma,
                           const float* __restrict__ beta) {
    const int b = blockIdx.x, tid = threadIdx.x;
    __shared__ float T[16 * 516];
    __shared__ float red[512];
    __shared__ float sc[16], sh[16], murs[4];

    for (int grp = 0; grp < 2; grp++) {
        const float4* xg = (const float4*)(x + (16 * b + 8 * grp) * N);
        float s = 0.f, s2 = 0.f;
        for (int i = tid; i < 8192; i += 256) {
            float4 v = xg[i];
            s  += (v.x + v.y) + (v.z + v.w);
            s2 += (v.x * v.x + v.y * v.y) + (v.z * v.z + v.w * v.w);
        }
        red[tid] = s; red[256 + tid] = s2;
        __syncthreads();
        for (int st = 128; st > 0; st >>= 1) {
            if (tid < st) { red[tid] += red[tid + st]; red[256 + tid] += red[256 + tid + st]; }
            __syncthreads();
        }
        if (tid == 0) {
            float mu = red[0] * (1.f / GELEMS);
            float var = red[256] * (1.f / GELEMS) - mu * mu;
            murs[grp] = mu; murs[2 + grp] = rsqrtf(var + GN_EPS);
        }
        __syncthreads();
    }
    if (tid < 16) {
        int grp = tid >> 3;
        float s = murs[2 + grp] * gamma[16 * b + tid];
        sc[tid] = s;
        sh[tid] = beta[16 * b + tid] - murs[grp] * s;
    }
    __syncthreads();

    uint32_t* hnw = (uint32_t*)g_hnb;
    for (int chunk = 0; chunk < 8; chunk++) {
        const int pc = chunk * 512;
        __syncthreads();
        for (int e = tid; e < 2048; e += 256) {
            int r = e >> 7, c4 = e & 127;
            *(float4*)(T + r * 516 + c4 * 4) =
                *(const float4*)(x + (16 * b + r) * N + pc + c4 * 4);
        }
        __syncthreads();
#pragma unroll
        for (int pp = 0; pp < 2; pp++) {
            const int pl = tid + pp * 256;
            float v[16];
#pragma unroll
            for (int c = 0; c < 16; c++)
                v[c] = fmaf(T[c * 516 + pl], sc[c], sh[c]);
            uint32_t wd[8];
#pragma unroll
            for (int j = 0; j < 8; j++)
                wd[wpos8(j)] = pk_bf2(v[2 * j], v[2 * j + 1]);
            uint4* dst = (uint4*)(hnw + (pc + pl) * 128 + b * 8);
            dst[0] = make_uint4(wd[0], wd[1], wd[2], wd[3]);
            dst[1] = make_uint4(wd[4], wd[5], wd[6], wd[7]);
        }
    }
}

// ---------------------------------------------------------------------------
// Kernel 1b: Wq/Wk/Wv -> bf16 [o][perm16 c] (validated).
// ---------------------------------------------------------------------------
__global__ void wcvt_kernel(const float* __restrict__ Wq,
                            const float* __restrict__ Wk,
                            const float* __restrict__ Wv) {
    const int z = blockIdx.y;
    const float* W = (z == 0) ? Wq : (z == 1) ? Wk : Wv;
    uint32_t* wbw = (uint32_t*)g_wb + z * 32768;
    int e = blockIdx.x * 256 + threadIdx.x;
    int o = e >> 7, c2 = e & 127;
    float2 wv = *(const float2*)(W + o * 256 + 2 * c2);
    wbw[o * 128 + (c2 >> 3) * 8 + wpos8(c2 & 7)] = pk_bf2(wv.x, wv.y);
}

// ---------------------------------------------------------------------------
// Kernel 1c: Wp -> tf32 fp32 words [o][perm8 c].
// ---------------------------------------------------------------------------
__global__ void wcvtp_kernel(const float* __restrict__ Wp) {
    int e = blockIdx.x * 256 + threadIdx.x;       // 0..65535
    int o = e >> 8, c = e & 255;
    g_wpt[o * 256 + (c & ~7) + wpos8(c & 7)] = tf32r(Wp[e]);
}

// ---------------------------------------------------------------------------
// Kernel 2: Q/K/V projection, bf16 mma (validated r8-r10).
// ---------------------------------------------------------------------------
__global__ __launch_bounds__(256, 1) void qkv_mma_kernel(
        const float* __restrict__ bq, const float* __restrict__ bk,
        const float* __restrict__ bv) {
    __shared__ uint32_t sbuf[10240];
    uint32_t* Aw = sbuf;
    uint32_t* Bw = sbuf + 128 * 40;

    const int tid = threadIdx.x;
    const int w = tid >> 5, lane = tid & 31;
    const int g = lane >> 2, tig = lane & 3;
    const int p0 = blockIdx.x * 128;
    const int o0 = blockIdx.y * 128;
    const int z  = blockIdx.z;
    const float* bias = (z == 0) ? bq : (z == 1) ? bk : bv;

    const uint32_t* hnw = (const uint32_t*)g_hnb;
    const uint32_t* wbw = (const uint32_t*)g_wb + z * 32768;

    float acc[16][4] = {};

    for (int ch = 0; ch < 4; ch++) {
        __syncthreads();
#pragma unroll
        for (int i = 0; i < 4; i++) {
            int e = i * 256 + tid;
            int r = e >> 3, c4 = e & 7;
            *(uint4*)(Aw + r * 40 + c4 * 4) =
                *(const uint4*)(hnw + (p0 + r) * 128 + ch * 32 + c4 * 4);
            *(uint4*)(Bw + r * 40 + c4 * 4) =
                *(const uint4*)(wbw + (o0 + r) * 128 + ch * 32 + c4 * 4);
        }
        __syncthreads();

        uint32_t a[4][4];
#pragma unroll
        for (int ks = 0; ks < 4; ks++) {
            uint2 t0 = *(const uint2*)(Aw + (w * 16 + g)     * 40 + ks * 8 + 2 * tig);
            uint2 t1 = *(const uint2*)(Aw + (w * 16 + g + 8) * 40 + ks * 8 + 2 * tig);
            a[ks][0] = t0.x; a[ks][1] = t1.x; a[ks][2] = t0.y; a[ks][3] = t1.y;
        }
#pragma unroll
        for (int nt = 0; nt < 16; nt++) {
            const uint32_t* bb = Bw + (nt * 8 + g) * 40 + 2 * tig;
#pragma unroll
            for (int ks = 0; ks < 4; ks++) {
                uint2 t = *(const uint2*)(bb + ks * 8);
                mma_bf16(acc[nt], a[ks][0], a[ks][1], a[ks][2], a[ks][3], t.x, t.y);
            }
        }
    }

    if (z < 2) {
        const float s = (z == 0) ? QSCALE2 : 1.f;
        uint32_t* dst = (uint32_t*)((z == 0) ? g_qb : g_kb);
        const int p = p0 + w * 16 + g;
#pragma unroll
        for (int nt = 0; nt < 16; nt++) {
            const int o = o0 + nt * 8 + 2 * tig;
            const float b0 = bias[o], b1 = bias[o + 1];
            const int wi = (o0 >> 4) * 8 + (nt >> 1) * 8 + 2 * tig + (nt & 1);
            dst[p * 128 + wi]       = pk_bf2((acc[nt][0] + b0) * s, (acc[nt][1] + b1) * s);
            dst[(p + 8) * 128 + wi] = pk_bf2((acc[nt][2] + b0) * s, (acc[nt][3] + b1) * s);
        }
    } else {
        __syncthreads();
        __nv_bfloat16* Vs = (__nv_bfloat16*)sbuf;
        const int plA = perm16(w * 16 + g), plB = perm16(w * 16 + g + 8);
#pragma unroll
        for (int nt = 0; nt < 16; nt++) {
            const int ol = nt * 8 + 2 * tig;
            const float b0 = bias[o0 + ol], b1 = bias[o0 + ol + 1];
            Vs[ol * 130 + plA]       = __float2bfloat16(acc[nt][0] + b0);
            Vs[(ol + 1) * 130 + plA] = __float2bfloat16(acc[nt][1] + b1);
            Vs[ol * 130 + plB]       = __float2bfloat16(acc[nt][2] + b0);
            Vs[(ol + 1) * 130 + plB] = __float2bfloat16(acc[nt][3] + b1);
        }
        __syncthreads();
        uint32_t* vtw = (uint32_t*)g_vtb;
        const uint32_t* vsw = (const uint32_t*)Vs;
#pragma unroll
        for (int i = 0; i < 32; i++) {
            int e = i * 256 + tid;
            int r = e >> 6, cc = e & 63;
            vtw[(o0 + r) * 2048 + (p0 >> 1) + cc] = vsw[r * 65 + cc];
        }
    }
}

// ---------------------------------------------------------------------------
// Kernel 3: attention, split-K x2, r10 compute, 3-stage cp.async ring with
// ONE syncthreads per tile. Dynamic smem 61440B (2 CTAs/SM).
// ---------------------------------------------------------------------------
#define PITCH 40
#define STG_W (2 * 64 * PITCH)
#define KT_PER (64 / NSPLIT)
#define ATTN_SMEM (3 * STG_W * 4)

__global__ __launch_bounds__(256, 2) void attn_mma_kernel() {
    extern __shared__ uint32_t dbuf[];

    const int tid  = threadIdx.x;
    const int w    = tid >> 5, lane = tid & 31;
    const int g    = lane >> 2, tig = lane & 3;
    const int head = blockIdx.y;
    const int q0   = blockIdx.x * 128;
    const int spl  = blockIdx.z;
    const int kt0  = spl * KT_PER;

    const __nv_bfloat16* gq  = g_qb  + head * HD;
    const __nv_bfloat16* gk  = g_kb  + head * HD + kt0 * 64 * C;
    const __nv_bfloat16* gvt = g_vtb + head * HD * N + kt0 * 64;

    uint32_t qa[4][4];
    {
        const int r0 = q0 + w * 16 + g;
#pragma unroll
        for (int ks = 0; ks < 4; ks++) {
            uint2 t0 = *(const uint2*)(gq +  r0      * C + ks * 16 + 4 * tig);
            uint2 t1 = *(const uint2*)(gq + (r0 + 8) * C + ks * 16 + 4 * tig);
            qa[ks][0] = t0.x; qa[ks][1] = t1.x; qa[ks][2] = t0.y; qa[ks][3] = t1.y;
        }
    }

    const uint32_t sb = smem_u32(dbuf);
    int rr[2], cc4[2];
#pragma unroll
    for (int i = 0; i < 2; i++) {
        int e = i * 256 + tid;
        rr[i] = e >> 3; cc4[i] = e & 7;
    }

    float oacc[8][4] = {};
    float l0 = 0.f, l1 = 0.f;

    // prologue: tiles 0,1 -> stages 0,1
#pragma unroll
    for (int t = 0; t < 2; t++) {
        const uint32_t db = sb + t * STG_W * 4;
        const __nv_bfloat16* ks_src = gk + t * 64 * C;
        const __nv_bfloat16* vs_src = gvt + t * 64;
#pragma unroll
        for (int i = 0; i < 2; i++) {
            cp16(db + (rr[i] * PITCH + cc4[i] * 4) * 4, ks_src + rr[i] * C + cc4[i] * 8);
            cp16(db + (64 * PITCH + rr[i] * PITCH + cc4[i] * 4) * 4,
                 vs_src + rr[i] * N + cc4[i] * 8);
        }
        CP_COMMIT();
    }

    for (int kt = 0; kt < KT_PER; kt++) {
        if (kt + 1 < KT_PER) { CP_WAIT1(); } else { CP_WAIT0(); }
        __syncthreads();   // tile kt visible to all; stage (kt+2)%3 consumed by all

        if (kt + 2 < KT_PER) {
            const uint32_t db = sb + ((kt + 2) % 3) * STG_W * 4;
            const __nv_bfloat16* ks_src = gk + (kt + 2) * 64 * C;
            const __nv_bfloat16* vs_src = gvt + (kt + 2) * 64;
#pragma unroll
            for (int i = 0; i < 2; i++) {
                cp16(db + (rr[i] * PITCH + cc4[i] * 4) * 4,
                     ks_src + rr[i] * C + cc4[i] * 8);
                cp16(db + (64 * PITCH + rr[i] * PITCH + cc4[i] * 4) * 4,
                     vs_src + rr[i] * N + cc4[i] * 8);
            }
            CP_COMMIT();
        }

        const uint32_t* Kc = dbuf + (kt % 3) * STG_W;
        const uint32_t* Vc = Kc + 64 * PITCH;

        float p[8][4];
#pragma unroll
        for (int nt = 0; nt < 8; nt++) {
            float s[4] = {};
            const uint32_t* kb = Kc + (nt * 8 + g) * PITCH + 2 * tig;
#pragma unroll
            for (int ks = 0; ks < 4; ks++) {
                uint2 b = *(const uint2*)(kb + ks * 8);
                mma_bf16(s, qa[ks][0], qa[ks][1], qa[ks][2], qa[ks][3], b.x, b.y);
            }
            p[nt][0] = ex2(s[0]); p[nt][1] = ex2(s[1]);
            p[nt][2] = ex2(s[2]); p[nt][3] = ex2(s[3]);
            l0 += p[nt][0] + p[nt][1];
            l1 += p[nt][2] + p[nt][3];
        }

#pragma unroll
        for (int ks = 0; ks < 4; ks++) {
            const uint32_t pa0 = pk_bf2(p[2 * ks][0],     p[2 * ks][1]);
            const uint32_t pa1 = pk_bf2(p[2 * ks][2],     p[2 * ks][3]);
            const uint32_t pa2 = pk_bf2(p[2 * ks + 1][0], p[2 * ks + 1][1]);
            const uint32_t pa3 = pk_bf2(p[2 * ks + 1][2], p[2 * ks + 1][3]);
            const uint32_t* vb = Vc + g * PITCH + ks * 8 + 2 * tig;
#pragma unroll
            for (int nt = 0; nt < 8; nt++) {
                uint2 b = *(const uint2*)(vb + nt * 8 * PITCH);
                mma_bf16(oacc[nt], pa0, pa1, pa2, pa3, b.x, b.y);
            }
        }
    }

    l0 += __shfl_xor_sync(0xffffffffu, l0, 1);
    l0 += __shfl_xor_sync(0xffffffffu, l0, 2);
    l1 += __shfl_xor_sync(0xffffffffu, l1, 1);
    l1 += __shfl_xor_sync(0xffffffffu, l1, 2);

    const int r0 = q0 + w * 16 + g;
    if (tig == 0) {
        g_pl[(spl * HEADS + head) * N + r0]     = l0;
        g_pl[(spl * HEADS + head) * N + r0 + 8] = l1;
    }
    float* po = g_po + spl * N * C;
#pragma unroll
    for (int nt = 0; nt < 8; nt++) {
        const int col = head * HD + nt * 8 + 2 * tig;
        *(float2*)(po + r0 * C + col)       = make_float2(oacc[nt][0], oacc[nt][1]);
        *(float2*)(po + (r0 + 8) * C + col) = make_float2(oacc[nt][2], oacc[nt][3]);
    }
}

// ---------------------------------------------------------------------------
// Kernel 3b: linv = 1/(l0+l1).
// ---------------------------------------------------------------------------
__global__ void linv_kernel() {
    const int i = blockIdx.x * 256 + threadIdx.x;
    g_linv[i] = 1.f / (g_pl[i] + g_pl[HEADS * N + i]);
}

// ---------------------------------------------------------------------------
// Kernel 3c: combine partials, normalize, TRANSPOSE to proj B layout:
// g_ot[p2][perm8 c] = tf32((po0+po1)[c*4096+p2] * linv). Block = 64c x 64p2.
// ---------------------------------------------------------------------------
__global__ void combine_t_kernel() {
    __shared__ float T[64 * 65];
    __shared__ float linv_s[64];
    const int tid = threadIdx.x;
    const int p0 = blockIdx.x * 64;
    const int c0 = blockIdx.y * 64;

    const int head = (p0 >> 6) & 3;
    const int pixoff = p0 >> 8;
    if (tid < 64)
        linv_s[tid] = g_linv[head * N + (c0 + tid) * 16 + pixoff];
    __syncthreads();

    const float* po0 = g_po;
    const float* po1 = g_po + N * C;
#pragma unroll
    for (int i = 0; i < 16; i++) {
        int idx = tid + i * 256;
        int cl = idx >> 6, pl = idx & 63;
        int f = (c0 + cl) * N + p0 + pl;
        T[cl * 65 + pl] = (po0[f] + po1[f]) * linv_s[cl];
    }
    __syncthreads();
#pragma unroll
    for (int i = 0; i < 16; i++) {
        int idx = tid + i * 256;
        int pl = idx >> 6, cl = idx & 63;
        int cperm = c0 + (cl & ~7) + wpos8(cl & 7);
        g_ot[(p0 + pl) * 256 + cperm] = tf32r(T[cl * 65 + pl]);
    }
}

// ---------------------------------------------------------------------------
// Kernel 4: proj via tf32 mma m16n8k8 + residual. CTA = 64 o x 128 p2,
// 128 threads (4 warps x 16 o-rows). grid (32, 4). k=256 in 8 chunks of 32.
// ---------------------------------------------------------------------------
__global__ __launch_bounds__(128, 2) void proj_mma_kernel(
        const float* __restrict__ bp,
        const float* __restrict__ x, float* __restrict__ out) {
    __shared__ uint32_t Aw[64 * 40];    // Wp tile  [o][perm8 c-chunk]
    __shared__ uint32_t Bw[128 * 40];   // g_ot tile [p2][perm8 c-chunk]

    const int tid = threadIdx.x;
    const int w = tid >> 5, lane = tid & 31;
    const int g = lane >> 2, tig = lane & 3;
    const int p0 = blockIdx.x * 128;
    const int o0 = blockIdx.y * 64;

    const uint32_t* wpt = (const uint32_t*)g_wpt;
    const uint32_t* otw = (const uint32_t*)g_ot;

    float acc[16][4] = {};

    for (int ch = 0; ch < 8; ch++) {
        __syncthreads();
#pragma unroll
        for (int i = 0; i < 4; i++) {               // A: 64x32 words = 512 uint4
            int e = i * 128 + tid;
            int r = e >> 3, q = e & 7;
            *(uint4*)(Aw + r * 40 + q * 4) =
                *(const uint4*)(wpt + (o0 + r) * 256 + ch * 32 + q * 4);
        }
#pragma unroll
        for (int i = 0; i < 8; i++) {               // B: 128x32 words = 1024 uint4
            int e = i * 128 + tid;
            int r = e >> 3, q = e & 7;
            *(uint4*)(Bw + r * 40 + q * 4) =
                *(const uint4*)(otw + (p0 + r) * 256 + ch * 32 + q * 4);
        }
        __syncthreads();

        uint32_t a[4][4];
#pragma unroll
        for (int ks = 0; ks < 4; ks++) {
            uint2 t0 = *(const uint2*)(Aw + (w * 16 + g)     * 40 + ks * 8 + 2 * tig);
            uint2 t1 = *(const uint2*)(Aw + (w * 16 + g + 8) * 40 + ks * 8 + 2 * tig);
            a[ks][0] = t0.x; a[ks][1] = t1.x; a[ks][2] = t0.y; a[ks][3] = t1.y;
        }
#pragma unroll
        for (int nt = 0; nt < 16; nt++) {
            const uint32_t* bb = Bw + (nt * 8 + g) * 40 + 2 * tig;
#pragma unroll
            for (int ks = 0; ks < 4; ks++) {
                uint2 t = *(const uint2*)(bb + ks * 8);
                mma_tf32(acc[nt], a[ks][0], a[ks][1], a[ks][2], a[ks][3], t.x, t.y);
            }
        }
    }

    const int oo = o0 + w * 16 + g;
    const float b0 = bp[oo], b1 = bp[oo + 8];
#pragma unroll
    for (int nt = 0; nt < 16; nt++) {
        const int pp = p0 + nt * 8 + 2 * tig;
        float2 x0 = *(const float2*)(x + oo * N + pp);
        float2 x1 = *(const float2*)(x + (oo + 8) * N + pp);
        *(float2*)(out + oo * N + pp) =
            make_float2(x0.x + b0 + acc[nt][0], x0.y + b0 + acc[nt][1]);
        *(float2*)(out + (oo + 8) * N + pp) =
            make_float2(x1.x + b1 + acc[nt][2], x1.y + b1 + acc[nt][3]);
    }
}

// ---------------------------------------------------------------------------
extern "C" void kernel_launch(void* const* d_in, const int* in_sizes, int n_in,
                              void* d_out, int out_size) {
    const float* x     = (const float*)d_in[0];
    const float* gamma = (const float*)d_in[1];
    const float* beta  = (const float*)d_in[2];
    const float* Wq    = (const float*)d_in[3];
    const float* bq    = (const float*)d_in[4];
    const float* Wk    = (const float*)d_in[5];
    const float* bk    = (const float*)d_in[6];
    const float* Wv    = (const float*)d_in[7];
    const float* bv    = (const float*)d_in[8];
    const float* Wp    = (const float*)d_in[9];
    const float* bp    = (const float*)d_in[10];
    float* out = (float*)d_out;

    cudaFuncSetAttribute(attn_mma_kernel,
                         cudaFuncAttributeMaxDynamicSharedMemorySize, ATTN_SMEM);

    gn2_kernel<<<16, 256>>>(x, gamma, beta);

    dim3 gw(128, 3);
    wcvt_kernel<<<gw, 256>>>(Wq, Wk, Wv);
    wcvtp_kernel<<<256, 256>>>(Wp);

    dim3 g2(N / 128, C / 128, 3);
    qkv_mma_kernel<<<g2, 256>>>(bq, bk, bv);

    dim3 g3(N / 128, HEADS, NSPLIT);
    attn_mma_kernel<<<g3, 256, ATTN_SMEM>>>();

    linv_kernel<<<HEADS * N / 256, 256>>>();

    dim3 gc(N / 64, C / 64);
    combine_t_kernel<<<gc, 256>>>();

    dim3 g4(N / 128, C / 64);
    proj_mma_kernel<<<g4, 128>>>(bp, x, out);
}

// round 14
// speedup vs baseline: 1.1586x; 1.0390x over previous
#include <cuda_runtime.h>
#include <cuda_bf16.h>
#include <cstdint>

#define C       256
#define N       4096
#define HEADS   4
#define HD      64
#define GROUPS  32
#define GSIZE   (C / GROUPS)
#define GELEMS  (GSIZE * N)
#define GN_EPS  1e-6f
// 0.125 * log2(e): softmax uses ex2 directly
#define QSCALE2 0.18033688011112042f
#define NSPLIT  2

// bf16 scratch. Channel (or key) index pair-permuted within 16-blocks
// ([0,1,8,9,2,3,10,11,4,5,12,13,6,7,14,15]) so MMA fragments are LDS.64.
__device__ __nv_bfloat16 g_hnb[N * C];     // groupnormed input [p][perm c]
__device__ __nv_bfloat16 g_wb [3 * C * C]; // weights bf16 [o][perm c]
__device__ __nv_bfloat16 g_qb [N * C];
__device__ __nv_bfloat16 g_kb [N * C];
__device__ __nv_bfloat16 g_vtb[C * N];     // V transposed [c][perm p]
__device__ float g_po[NSPLIT * N * C];     // unnormalized O partials
__device__ float g_pl[NSPLIT * HEADS * N]; // l partials [split][head][p]
__device__ float g_ot [N * C];             // proj B operand [p2][perm8 c], tf32
__device__ float g_wpt[C * C];             // Wp tf32 [o][perm8 c]

__device__ __forceinline__ int perm16(int i) {
    int b = i & ~15, l = i & 15, j = l >> 1, o = l & 1;
    int p = (j < 4) ? 4 * j : 4 * (j - 4) + 2;
    return b + p + o;
}
__device__ __forceinline__ int wpos8(int j) {
    return (j < 4) ? 2 * j : 2 * (j - 4) + 1;
}
__device__ __forceinline__ uint32_t pk_bf2(float lo, float hi) {
    uint32_t d;
    asm("cvt.rn.bf16x2.f32 %0, %1, %2;" : "=r"(d) : "f"(hi), "f"(lo));
    return d;
}
__device__ __forceinline__ float ex2(float x) {
    float r;
    asm("ex2.approx.f32 %0, %1;" : "=f"(r) : "f"(x));
    return r;
}
__device__ __forceinline__ float tf32r(float f) {
    uint32_t u;
    asm("cvt.rna.tf32.f32 %0, %1;" : "=r"(u) : "f"(f));
    return __uint_as_float(u);
}
__device__ __forceinline__ void mma_bf16(float c[4],
        uint32_t a0, uint32_t a1, uint32_t a2, uint32_t a3,
        uint32_t b0, uint32_t b1) {
    asm volatile("mma.sync.aligned.m16n8k16.row.col.f32.bf16.bf16.f32 "
                 "{%0,%1,%2,%3}, {%4,%5,%6,%7}, {%8,%9}, {%0,%1,%2,%3};"
                 : "+f"(c[0]), "+f"(c[1]), "+f"(c[2]), "+f"(c[3])
                 : "r"(a0), "r"(a1), "r"(a2), "r"(a3), "r"(b0), "r"(b1));
}
__device__ __forceinline__ void mma_tf32(float c[4],
        uint32_t a0, uint32_t a1, uint32_t a2, uint32_t a3,
        uint32_t b0, uint32_t b1) {
    asm volatile("mma.sync.aligned.m16n8k8.row.col.f32.tf32.tf32.f32 "
                 "{%0,%1,%2,%3}, {%4,%5,%6,%7}, {%8,%9}, {%0,%1,%2,%3};"
                 : "+f"(c[0]), "+f"(c[1]), "+f"(c[2]), "+f"(c[3])
                 : "r"(a0), "r"(a1), "r"(a2), "r"(a3), "r"(b0), "r"(b1));
}
__device__ __forceinline__ uint32_t smem_u32(const void* p) {
    uint32_t a;
    asm("{ .reg .u64 t; cvta.to.shared.u64 t, %1; cvt.u32.u64 %0, t; }"
        : "=r"(a) : "l"(p));
    return a;
}
__device__ __forceinline__ void cp16(uint32_t d, const void* s) {
    asm volatile("cp.async.cg.shared.global [%0], [%1], 16;" :: "r"(d), "l"(s));
}
#define CP_COMMIT() asm volatile("cp.async.commit_group;" ::: "memory")
#define CP_WAIT0()  asm volatile("cp.async.wait_group 0;" ::: "memory")
#define CP_WAIT1()  asm volatile("cp.async.wait_group 1;" ::: "memory")

// ---------------------------------------------------------------------------
// Kernel 1: GroupNorm stats + apply -> g_hnb bf16 [p][perm c] (validated).
// ---------------------------------------------------------------------------
__global__ void gn2_kernel(const float* __restrict__ x,
                           const float* __restrict__ gamma,
                           const float* __restrict__ beta) {
    const int b = blockIdx.x, tid = threadIdx.x;
    __shared__ float T[16 * 516];
    __shared__ float red[512];
    __shared__ float sc[16], sh[16], murs[4];

    for (int grp = 0; grp < 2; grp++) {
        const float4* xg = (const float4*)(x + (16 * b + 8 * grp) * N);
        float s = 0.f, s2 = 0.f;
        for (int i = tid; i < 8192; i += 256) {
            float4 v = xg[i];
            s  += (v.x + v.y) + (v.z + v.w);
            s2 += (v.x * v.x + v.y * v.y) + (v.z * v.z + v.w * v.w);
        }
        red[tid] = s; red[256 + tid] = s2;
        __syncthreads();
        for (int st = 128; st > 0; st >>= 1) {
            if (tid < st) { red[tid] += red[tid + st]; red[256 + tid] += red[256 + tid + st]; }
            __syncthreads();
        }
        if (tid == 0) {
            float mu = red[0] * (1.f / GELEMS);
            float var = red[256] * (1.f / GELEMS) - mu * mu;
            murs[grp] = mu; murs[2 + grp] = rsqrtf(var + GN_EPS);
        }
        __syncthreads();
    }
    if (tid < 16) {
        int grp = tid >> 3;
        float s = murs[2 + grp] * gamma[16 * b + tid];
        sc[tid] = s;
        sh[tid] = beta[16 * b + tid] - murs[grp] * s;
    }
    __syncthreads();

    uint32_t* hnw = (uint32_t*)g_hnb;
    for (int chunk = 0; chunk < 8; chunk++) {
        const int pc = chunk * 512;
        __syncthreads();
        for (int e = tid; e < 2048; e += 256) {
            int r = e >> 7, c4 = e & 127;
            *(float4*)(T + r * 516 + c4 * 4) =
                *(const float4*)(x + (16 * b + r) * N + pc + c4 * 4);
        }
        __syncthreads();
#pragma unroll
        for (int pp = 0; pp < 2; pp++) {
            const int pl = tid + pp * 256;
            float v[16];
#pragma unroll
            for (int c = 0; c < 16; c++)
                v[c] = fmaf(T[c * 516 + pl], sc[c], sh[c]);
            uint32_t wd[8];
#pragma unroll
            for (int j = 0; j < 8; j++)
                wd[wpos8(j)] = pk_bf2(v[2 * j], v[2 * j + 1]);
            uint4* dst = (uint4*)(hnw + (pc + pl) * 128 + b * 8);
            dst[0] = make_uint4(wd[0], wd[1], wd[2], wd[3]);
            dst[1] = make_uint4(wd[4], wd[5], wd[6], wd[7]);
        }
    }
}

// ---------------------------------------------------------------------------
// Kernel 1b: weight convert, merged. z<3: Wq/Wk/Wv -> bf16 [o][perm16 c].
// z==3: Wp -> tf32 [o][perm8 c]. grid (128, 4) x 256.
// ---------------------------------------------------------------------------
__global__ void wcvt_kernel(const float* __restrict__ Wq,
                            const float* __restrict__ Wk,
                            const float* __restrict__ Wv,
                            const float* __restrict__ Wp) {
    const int z = blockIdx.y;
    int e = blockIdx.x * 256 + threadIdx.x;      // 0..32767 float2
    int o = e >> 7, c2 = e & 127;
    if (z < 3) {
        const float* W = (z == 0) ? Wq : (z == 1) ? Wk : Wv;
        uint32_t* wbw = (uint32_t*)g_wb + z * 32768;
        float2 wv = *(const float2*)(W + o * 256 + 2 * c2);
        wbw[o * 128 + (c2 >> 3) * 8 + wpos8(c2 & 7)] = pk_bf2(wv.x, wv.y);
    } else {
        float2 wv = *(const float2*)(Wp + o * 256 + 2 * c2);
        int cbase = (2 * c2) & ~7, cl = (2 * c2) & 7;
        g_wpt[o * 256 + cbase + wpos8(cl)]     = tf32r(wv.x);
        g_wpt[o * 256 + cbase + wpos8(cl + 1)] = tf32r(wv.y);
    }
}

// ---------------------------------------------------------------------------
// Kernel 2: Q/K/V projection, bf16 mma, cp.async double-buffered chunks.
// Dynamic smem: 2 stages x (A 128x40 + B 128x40) words = 80KB, 1 CTA/SM.
// ---------------------------------------------------------------------------
#define QKV_STG_W (2 * 128 * 40)
#define QKV_SMEM  (2 * QKV_STG_W * 4)

__global__ __launch_bounds__(256, 1) void qkv_mma_kernel(
        const float* __restrict__ bq, const float* __restrict__ bk,
        const float* __restrict__ bv) {
    extern __shared__ uint32_t sbuf[];

    const int tid = threadIdx.x;
    const int w = tid >> 5, lane = tid & 31;
    const int g = lane >> 2, tig = lane & 3;
    const int p0 = blockIdx.x * 128;
    const int o0 = blockIdx.y * 128;
    const int z  = blockIdx.z;
    const float* bias = (z == 0) ? bq : (z == 1) ? bk : bv;

    const uint32_t* hnw = (const uint32_t*)g_hnb;
    const uint32_t* wbw = (const uint32_t*)g_wb + z * 32768;

    const uint32_t sb = smem_u32(sbuf);
    // per-thread cp.async coords: 4 uint4 each for A and B per chunk
    int rr[4], q4[4];
#pragma unroll
    for (int i = 0; i < 4; i++) {
        int e = i * 256 + tid;
        rr[i] = e >> 3; q4[i] = e & 7;
    }

    float acc[16][4] = {};

    // prologue: chunk 0 -> stage 0
#pragma unroll
    for (int i = 0; i < 4; i++) {
        cp16(sb + (rr[i] * 40 + q4[i] * 4) * 4,
             hnw + (p0 + rr[i]) * 128 + q4[i] * 4);
        cp16(sb + ((128 * 40) + rr[i] * 40 + q4[i] * 4) * 4,
             wbw + (o0 + rr[i]) * 128 + q4[i] * 4);
    }
    CP_COMMIT();

    for (int ch = 0; ch < 4; ch++) {
        CP_WAIT0();
        __syncthreads();
        if (ch < 3) {
            const uint32_t db = sb + ((ch + 1) & 1) * QKV_STG_W * 4;
#pragma unroll
            for (int i = 0; i < 4; i++) {
                cp16(db + (rr[i] * 40 + q4[i] * 4) * 4,
                     hnw + (p0 + rr[i]) * 128 + (ch + 1) * 32 + q4[i] * 4);
                cp16(db + ((128 * 40) + rr[i] * 40 + q4[i] * 4) * 4,
                     wbw + (o0 + rr[i]) * 128 + (ch + 1) * 32 + q4[i] * 4);
            }
            CP_COMMIT();
        }
        const uint32_t* Aw = sbuf + (ch & 1) * QKV_STG_W;
        const uint32_t* Bw = Aw + 128 * 40;

        uint32_t a[4][4];
#pragma unroll
        for (int ks = 0; ks < 4; ks++) {
            uint2 t0 = *(const uint2*)(Aw + (w * 16 + g)     * 40 + ks * 8 + 2 * tig);
            uint2 t1 = *(const uint2*)(Aw + (w * 16 + g + 8) * 40 + ks * 8 + 2 * tig);
            a[ks][0] = t0.x; a[ks][1] = t1.x; a[ks][2] = t0.y; a[ks][3] = t1.y;
        }
#pragma unroll
        for (int nt = 0; nt < 16; nt++) {
            const uint32_t* bb = Bw + (nt * 8 + g) * 40 + 2 * tig;
#pragma unroll
            for (int ks = 0; ks < 4; ks++) {
                uint2 t = *(const uint2*)(bb + ks * 8);
                mma_bf16(acc[nt], a[ks][0], a[ks][1], a[ks][2], a[ks][3], t.x, t.y);
            }
        }
    }

    if (z < 2) {
        const float s = (z == 0) ? QSCALE2 : 1.f;
        uint32_t* dst = (uint32_t*)((z == 0) ? g_qb : g_kb);
        const int p = p0 + w * 16 + g;
#pragma unroll
        for (int nt = 0; nt < 16; nt++) {
            const int o = o0 + nt * 8 + 2 * tig;
            const float b0 = bias[o], b1 = bias[o + 1];
            const int wi = (o0 >> 4) * 8 + (nt >> 1) * 8 + 2 * tig + (nt & 1);
            dst[p * 128 + wi]       = pk_bf2((acc[nt][0] + b0) * s, (acc[nt][1] + b1) * s);
            dst[(p + 8) * 128 + wi] = pk_bf2((acc[nt][2] + b0) * s, (acc[nt][3] + b1) * s);
        }
    } else {
        __syncthreads();
        __nv_bfloat16* Vs = (__nv_bfloat16*)sbuf;
        const int plA = perm16(w * 16 + g), plB = perm16(w * 16 + g + 8);
#pragma unroll
        for (int nt = 0; nt < 16; nt++) {
            const int ol = nt * 8 + 2 * tig;
            const float b0 = bias[o0 + ol], b1 = bias[o0 + ol + 1];
            Vs[ol * 130 + plA]       = __float2bfloat16(acc[nt][0] + b0);
            Vs[(ol + 1) * 130 + plA] = __float2bfloat16(acc[nt][1] + b1);
            Vs[ol * 130 + plB]       = __float2bfloat16(acc[nt][2] + b0);
            Vs[(ol + 1) * 130 + plB] = __float2bfloat16(acc[nt][3] + b1);
        }
        __syncthreads();
        uint32_t* vtw = (uint32_t*)g_vtb;
        const uint32_t* vsw = (const uint32_t*)Vs;
#pragma unroll
        for (int i = 0; i < 32; i++) {
            int e = i * 256 + tid;
            int r = e >> 6, cc = e & 63;
            vtw[(o0 + r) * 2048 + (p0 >> 1) + cc] = vsw[r * 65 + cc];
        }
    }
}

// ---------------------------------------------------------------------------
// Kernel 3: attention, split-K x2, 3-stage cp.async ring, one barrier/tile
// (validated r13).
// ---------------------------------------------------------------------------
#define PITCH 40
#define STG_W (2 * 64 * PITCH)
#define KT_PER (64 / NSPLIT)
#define ATTN_SMEM (3 * STG_W * 4)

__global__ __launch_bounds__(256, 2) void attn_mma_kernel() {
    extern __shared__ uint32_t dbuf[];

    const int tid  = threadIdx.x;
    const int w    = tid >> 5, lane = tid & 31;
    const int g    = lane >> 2, tig = lane & 3;
    const int head = blockIdx.y;
    const int q0   = blockIdx.x * 128;
    const int spl  = blockIdx.z;
    const int kt0  = spl * KT_PER;

    const __nv_bfloat16* gq  = g_qb  + head * HD;
    const __nv_bfloat16* gk  = g_kb  + head * HD + kt0 * 64 * C;
    const __nv_bfloat16* gvt = g_vtb + head * HD * N + kt0 * 64;

    uint32_t qa[4][4];
    {
        const int r0 = q0 + w * 16 + g;
#pragma unroll
        for (int ks = 0; ks < 4; ks++) {
            uint2 t0 = *(const uint2*)(gq +  r0      * C + ks * 16 + 4 * tig);
            uint2 t1 = *(const uint2*)(gq + (r0 + 8) * C + ks * 16 + 4 * tig);
            qa[ks][0] = t0.x; qa[ks][1] = t1.x; qa[ks][2] = t0.y; qa[ks][3] = t1.y;
        }
    }

    const uint32_t sb = smem_u32(dbuf);
    int rr[2], cc4[2];
#pragma unroll
    for (int i = 0; i < 2; i++) {
        int e = i * 256 + tid;
        rr[i] = e >> 3; cc4[i] = e & 7;
    }

    float oacc[8][4] = {};
    float l0 = 0.f, l1 = 0.f;

#pragma unroll
    for (int t = 0; t < 2; t++) {
        const uint32_t db = sb + t * STG_W * 4;
        const __nv_bfloat16* ks_src = gk + t * 64 * C;
        const __nv_bfloat16* vs_src = gvt + t * 64;
#pragma unroll
        for (int i = 0; i < 2; i++) {
            cp16(db + (rr[i] * PITCH + cc4[i] * 4) * 4, ks_src + rr[i] * C + cc4[i] * 8);
            cp16(db + (64 * PITCH + rr[i] * PITCH + cc4[i] * 4) * 4,
                 vs_src + rr[i] * N + cc4[i] * 8);
        }
        CP_COMMIT();
    }

    for (int kt = 0; kt < KT_PER; kt++) {
        if (kt + 1 < KT_PER) { CP_WAIT1(); } else { CP_WAIT0(); }
        __syncthreads();

        if (kt + 2 < KT_PER) {
            const uint32_t db = sb + ((kt + 2) % 3) * STG_W * 4;
            const __nv_bfloat16* ks_src = gk + (kt + 2) * 64 * C;
            const __nv_bfloat16* vs_src = gvt + (kt + 2) * 64;
#pragma unroll
            for (int i = 0; i < 2; i++) {
                cp16(db + (rr[i] * PITCH + cc4[i] * 4) * 4,
                     ks_src + rr[i] * C + cc4[i] * 8);
                cp16(db + (64 * PITCH + rr[i] * PITCH + cc4[i] * 4) * 4,
                     vs_src + rr[i] * N + cc4[i] * 8);
            }
            CP_COMMIT();
        }

        const uint32_t* Kc = dbuf + (kt % 3) * STG_W;
        const uint32_t* Vc = Kc + 64 * PITCH;

        float p[8][4];
#pragma unroll
        for (int nt = 0; nt < 8; nt++) {
            float s[4] = {};
            const uint32_t* kb = Kc + (nt * 8 + g) * PITCH + 2 * tig;
#pragma unroll
            for (int ks = 0; ks < 4; ks++) {
                uint2 b = *(const uint2*)(kb + ks * 8);
                mma_bf16(s, qa[ks][0], qa[ks][1], qa[ks][2], qa[ks][3], b.x, b.y);
            }
            p[nt][0] = ex2(s[0]); p[nt][1] = ex2(s[1]);
            p[nt][2] = ex2(s[2]); p[nt][3] = ex2(s[3]);
            l0 += p[nt][0] + p[nt][1];
            l1 += p[nt][2] + p[nt][3];
        }

#pragma unroll
        for (int ks = 0; ks < 4; ks++) {
            const uint32_t pa0 = pk_bf2(p[2 * ks][0],     p[2 * ks][1]);
            const uint32_t pa1 = pk_bf2(p[2 * ks][2],     p[2 * ks][3]);
            const uint32_t pa2 = pk_bf2(p[2 * ks + 1][0], p[2 * ks + 1][1]);
            const uint32_t pa3 = pk_bf2(p[2 * ks + 1][2], p[2 * ks + 1][3]);
            const uint32_t* vb = Vc + g * PITCH + ks * 8 + 2 * tig;
#pragma unroll
            for (int nt = 0; nt < 8; nt++) {
                uint2 b = *(const uint2*)(vb + nt * 8 * PITCH);
                mma_bf16(oacc[nt], pa0, pa1, pa2, pa3, b.x, b.y);
            }
        }
    }

    l0 += __shfl_xor_sync(0xffffffffu, l0, 1);
    l0 += __shfl_xor_sync(0xffffffffu, l0, 2);
    l1 += __shfl_xor_sync(0xffffffffu, l1, 1);
    l1 += __shfl_xor_sync(0xffffffffu, l1, 2);

    const int r0 = q0 + w * 16 + g;
    if (tig == 0) {
        g_pl[(spl * HEADS + head) * N + r0]     = l0;
        g_pl[(spl * HEADS + head) * N + r0 + 8] = l1;
    }
    float* po = g_po + spl * N * C;
#pragma unroll
    for (int nt = 0; nt < 8; nt++) {
        const int col = head * HD + nt * 8 + 2 * tig;
        *(float2*)(po + r0 * C + col)       = make_float2(oacc[nt][0], oacc[nt][1]);
        *(float2*)(po + (r0 + 8) * C + col) = make_float2(oacc[nt][2], oacc[nt][3]);
    }
}

// ---------------------------------------------------------------------------
// Kernel 3c: combine partials (+inline 1/l), normalize, transpose to proj B
// layout g_ot[p2][perm8 c] (tf32). Block = 64c x 64p2.
// ---------------------------------------------------------------------------
__global__ void combine_t_kernel() {
    __shared__ float T[64 * 65];
    __shared__ float linv_s[64];
    const int tid = threadIdx.x;
    const int p0 = blockIdx.x * 64;
    const int c0 = blockIdx.y * 64;

    const int head = (p0 >> 6) & 3;
    const int pixoff = p0 >> 8;
    if (tid < 64) {
        int pidx = head * N + (c0 + tid) * 16 + pixoff;
        linv_s[tid] = 1.f / (g_pl[pidx] + g_pl[HEADS * N + pidx]);
    }
    __syncthreads();

    const float* po0 = g_po;
    const float* po1 = g_po + N * C;
#pragma unroll
    for (int i = 0; i < 16; i++) {
        int idx = tid + i * 256;
        int cl = idx >> 6, pl = idx & 63;
        int f = (c0 + cl) * N + p0 + pl;
        T[cl * 65 + pl] = (po0[f] + po1[f]) * linv_s[cl];
    }
    __syncthreads();
#pragma unroll
    for (int i = 0; i < 16; i++) {
        int idx = tid + i * 256;
        int pl = idx >> 6, cl = idx & 63;
        int cperm = c0 + (cl & ~7) + wpos8(cl & 7);
        g_ot[(p0 + pl) * 256 + cperm] = tf32r(T[cl * 65 + pl]);
    }
}

// ---------------------------------------------------------------------------
// Kernel 4: proj via tf32 mma + residual (validated r13).
// ---------------------------------------------------------------------------
__global__ __launch_bounds__(128, 2) void proj_mma_kernel(
        const float* __restrict__ bp,
        const float* __restrict__ x, float* __restrict__ out) {
    __shared__ uint32_t Aw[64 * 40];
    __shared__ uint32_t Bw[128 * 40];

    const int tid = threadIdx.x;
    const int w = tid >> 5, lane = tid & 31;
    const int g = lane >> 2, tig = lane & 3;
    const int p0 = blockIdx.x * 128;
    const int o0 = blockIdx.y * 64;

    const uint32_t* wpt = (const uint32_t*)g_wpt;
    const uint32_t* otw = (const uint32_t*)g_ot;

    float acc[16][4] = {};

    for (int ch = 0; ch < 8; ch++) {
        __syncthreads();
#pragma unroll
        for (int i = 0; i < 4; i++) {
            int e = i * 128 + tid;
            int r = e >> 3, q = e & 7;
            *(uint4*)(Aw + r * 40 + q * 4) =
                *(const uint4*)(wpt + (o0 + r) * 256 + ch * 32 + q * 4);
        }
#pragma unroll
        for (int i = 0; i < 8; i++) {
            int e = i * 128 + tid;
            int r = e >> 3, q = e & 7;
            *(uint4*)(Bw + r * 40 + q * 4) =
                *(const uint4*)(otw + (p0 + r) * 256 + ch * 32 + q * 4);
        }
        __syncthreads();

        uint32_t a[4][4];
#pragma unroll
        for (int ks = 0; ks < 4; ks++) {
            uint2 t0 = *(const uint2*)(Aw + (w * 16 + g)     * 40 + ks * 8 + 2 * tig);
            uint2 t1 = *(const uint2*)(Aw + (w * 16 + g + 8) * 40 + ks * 8 + 2 * tig);
            a[ks][0] = t0.x; a[ks][1] = t1.x; a[ks][2] = t0.y; a[ks][3] = t1.y;
        }
#pragma unroll
        for (int nt = 0; nt < 16; nt++) {
            const uint32_t* bb = Bw + (nt * 8 + g) * 40 + 2 * tig;
#pragma unroll
            for (int ks = 0; ks < 4; ks++) {
                uint2 t = *(const uint2*)(bb + ks * 8);
                mma_tf32(acc[nt], a[ks][0], a[ks][1], a[ks][2], a[ks][3], t.x, t.y);
            }
        }
    }

    const int oo = o0 + w * 16 + g;
    const float b0 = bp[oo], b1 = bp[oo + 8];
#pragma unroll
    for (int nt = 0; nt < 16; nt++) {
        const int pp = p0 + nt * 8 + 2 * tig;
        float2 x0 = *(const float2*)(x + oo * N + pp);
        float2 x1 = *(const float2*)(x + (oo + 8) * N + pp);
        *(float2*)(out + oo * N + pp) =
            make_float2(x0.x + b0 + acc[nt][0], x0.y + b0 + acc[nt][1]);
        *(float2*)(out + (oo + 8) * N + pp) =
            make_float2(x1.x + b1 + acc[nt][2], x1.y + b1 + acc[nt][3]);
    }
}

// ---------------------------------------------------------------------------
extern "C" void kernel_launch(void* const* d_in, const int* in_sizes, int n_in,
                              void* d_out, int out_size) {
    const float* x     = (const float*)d_in[0];
    const float* gamma = (const float*)d_in[1];
    const float* beta  = (const float*)d_in[2];
    const float* Wq    = (const float*)d_in[3];
    const float* bq    = (const float*)d_in[4];
    const float* Wk    = (const float*)d_in[5];
    const float* bk    = (const float*)d_in[6];
    const float* Wv    = (const float*)d_in[7];
    const float* bv    = (const float*)d_in[8];
    const float* Wp    = (const float*)d_in[9];
    const float* bp    = (const float*)d_in[10];
    float* out = (float*)d_out;

    cudaFuncSetAttribute(attn_mma_kernel,
                         cudaFuncAttributeMaxDynamicSharedMemorySize, ATTN_SMEM);
    cudaFuncSetAttribute(qkv_mma_kernel,
                         cudaFuncAttributeMaxDynamicSharedMemorySize, QKV_SMEM);

    gn2_kernel<<<16, 256>>>(x, gamma, beta);

    dim3 gw(128, 4);
    wcvt_kernel<<<gw, 256>>>(Wq, Wk, Wv, Wp);

    dim3 g2(N / 128, C / 128, 3);
    qkv_mma_kernel<<<g2, 256, QKV_SMEM>>>(bq, bk, bv);

    dim3 g3(N / 128, HEADS, NSPLIT);
    attn_mma_kernel<<<g3, 256, ATTN_SMEM>>>();

    dim3 gc(N / 64, C / 64);
    combine_t_kernel<<<gc, 256>>>();

    dim3 g4(N / 128, C / 64);
    proj_mma_kernel<<<g4, 128>>>(bp, x, out);
}

// round 15
// speedup vs baseline: 1.2534x; 1.0818x over previous
#include <cuda_runtime.h>
#include <cuda_bf16.h>
#include <cstdint>

#define C       256
#define N       4096
#define HEADS   4
#define HD      64
#define GROUPS  32
#define GSIZE   (C / GROUPS)
#define GELEMS  (GSIZE * N)
#define GN_EPS  1e-6f
// 0.125 * log2(e): softmax uses ex2 directly
#define QSCALE2 0.18033688011112042f
#define NSPLIT  4

// bf16 scratch. Channel (or key) index pair-permuted within 16-blocks
// ([0,1,8,9,2,3,10,11,4,5,12,13,6,7,14,15]) so MMA fragments are LDS.64.
__device__ __nv_bfloat16 g_hnb[N * C];     // groupnormed input [p][perm c]
__device__ __nv_bfloat16 g_wb [3 * C * C]; // weights bf16 [o][perm c]
__device__ __nv_bfloat16 g_qb [N * C];
__device__ __nv_bfloat16 g_kb [N * C];
__device__ __nv_bfloat16 g_vtb[C * N];     // V transposed [c][perm p]
__device__ float g_po[NSPLIT * N * C];     // unnormalized O partials
__device__ float g_pl[NSPLIT * HEADS * N]; // l partials [split][head][p]
__device__ float g_ot [N * C];             // proj B operand [p2][perm8 c], tf32
__device__ float g_wpt[C * C];             // Wp tf32 [o][perm8 c]
__device__ float g_gs [GROUPS * 8];        // GN partial sums [group][slice]
__device__ float g_gs2[GROUPS * 8];        // GN partial sumsq

__device__ __forceinline__ int perm16(int i) {
    int b = i & ~15, l = i & 15, j = l >> 1, o = l & 1;
    int p = (j < 4) ? 4 * j : 4 * (j - 4) + 2;
    return b + p + o;
}
__device__ __forceinline__ int wpos8(int j) {
    return (j < 4) ? 2 * j : 2 * (j - 4) + 1;
}
__device__ __forceinline__ uint32_t pk_bf2(float lo, float hi) {
    uint32_t d;
    asm("cvt.rn.bf16x2.f32 %0, %1, %2;" : "=r"(d) : "f"(hi), "f"(lo));
    return d;
}
__device__ __forceinline__ float ex2(float x) {
    float r;
    asm("ex2.approx.f32 %0, %1;" : "=f"(r) : "f"(x));
    return r;
}
__device__ __forceinline__ float tf32r(float f) {
    uint32_t u;
    asm("cvt.rna.tf32.f32 %0, %1;" : "=r"(u) : "f"(f));
    return __uint_as_float(u);
}
__device__ __forceinline__ void mma_bf16(float c[4],
        uint32_t a0, uint32_t a1, uint32_t a2, uint32_t a3,
        uint32_t b0, uint32_t b1) {
    asm volatile("mma.sync.aligned.m16n8k16.row.col.f32.bf16.bf16.f32 "
                 "{%0,%1,%2,%3}, {%4,%5,%6,%7}, {%8,%9}, {%0,%1,%2,%3};"
                 : "+f"(c[0]), "+f"(c[1]), "+f"(c[2]), "+f"(c[3])
                 : "r"(a0), "r"(a1), "r"(a2), "r"(a3), "r"(b0), "r"(b1));
}
__device__ __forceinline__ void mma_tf32(float c[4],
        uint32_t a0, uint32_t a1, uint32_t a2, uint32_t a3,
        uint32_t b0, uint32_t b1) {
    asm volatile("mma.sync.aligned.m16n8k8.row.col.f32.tf32.tf32.f32 "
                 "{%0,%1,%2,%3}, {%4,%5,%6,%7}, {%8,%9}, {%0,%1,%2,%3};"
                 : "+f"(c[0]), "+f"(c[1]), "+f"(c[2]), "+f"(c[3])
                 : "r"(a0), "r"(a1), "r"(a2), "r"(a3), "r"(b0), "r"(b1));
}
__device__ __forceinline__ uint32_t smem_u32(const void* p) {
    uint32_t a;
    asm("{ .reg .u64 t; cvta.to.shared.u64 t, %1; cvt.u32.u64 %0, t; }"
        : "=r"(a) : "l"(p));
    return a;
}
__device__ __forceinline__ void cp16(uint32_t d, const void* s) {
    asm volatile("cp.async.cg.shared.global [%0], [%1], 16;" :: "r"(d), "l"(s));
}
#define CP_COMMIT() asm volatile("cp.async.commit_group;" ::: "memory")
#define CP_WAIT0()  asm volatile("cp.async.wait_group 0;" ::: "memory")
#define CP_WAIT1()  asm volatile("cp.async.wait_group 1;" ::: "memory")

// ---------------------------------------------------------------------------
// Kernel 1a: GN partial stats. grid (32 groups, 8 slices) x 256.
// Slice s: 8 channels x pixels [s*512, s*512+512).
// ---------------------------------------------------------------------------
__global__ void gn_stats_kernel(const float* __restrict__ x) {
    const int g = blockIdx.x, sl = blockIdx.y, tid = threadIdx.x;
    float s = 0.f, s2 = 0.f;
#pragma unroll
    for (int i = 0; i < 4; i++) {
        int e = i * 256 + tid;               // 0..1023 float4 within slice
        int c = e >> 7, q = e & 127;
        float4 v = *(const float4*)(x + (g * 8 + c) * N + sl * 512 + q * 4);
        s  += (v.x + v.y) + (v.z + v.w);
        s2 += (v.x * v.x + v.y * v.y) + (v.z * v.z + v.w * v.w);
    }
    __shared__ float r1[256], r2[256];
    r1[tid] = s; r2[tid] = s2;
    __syncthreads();
    for (int st = 128; st > 0; st >>= 1) {
        if (tid < st) { r1[tid] += r1[tid + st]; r2[tid] += r2[tid + st]; }
        __syncthreads();
    }
    if (tid == 0) {
        g_gs [g * 8 + sl] = r1[0];
        g_gs2[g * 8 + sl] = r2[0];
    }
}

// ---------------------------------------------------------------------------
// Kernel 1b: GN apply -> g_hnb bf16 [p][perm16 c]. grid (8 chunks, 16 b) x 256.
// Block (chunk, b): 16 channels (groups 2b,2b+1) x 512 pixels.
// ---------------------------------------------------------------------------
__global__ void gn_apply_kernel(const float* __restrict__ x,
                                const float* __restrict__ gamma,
                                const float* __restrict__ beta) {
    const int chunk = blockIdx.x, b = blockIdx.y, tid = threadIdx.x;
    __shared__ float T[16 * 516];
    __shared__ float sc[16], sh[16], murs[4];

    if (tid < 2) {
        float s = 0.f, s2 = 0.f;
#pragma unroll
        for (int i = 0; i < 8; i++) {
            s  += g_gs [(2 * b + tid) * 8 + i];
            s2 += g_gs2[(2 * b + tid) * 8 + i];
        }
        float mu = s * (1.f / GELEMS);
        float var = s2 * (1.f / GELEMS) - mu * mu;
        murs[tid] = mu; murs[2 + tid] = rsqrtf(var + GN_EPS);
    }
    __syncthreads();
    if (tid < 16) {
        int grp = tid >> 3;
        float s = murs[2 + grp] * gamma[16 * b + tid];
        sc[tid] = s;
        sh[tid] = beta[16 * b + tid] - murs[grp] * s;
    }

    const int pc = chunk * 512;
    for (int e = tid; e < 2048; e += 256) {
        int r = e >> 7, c4 = e & 127;
        *(float4*)(T + r * 516 + c4 * 4) =
            *(const float4*)(x + (16 * b + r) * N + pc + c4 * 4);
    }
    __syncthreads();

    uint32_t* hnw = (uint32_t*)g_hnb;
#pragma unroll
    for (int pp = 0; pp < 2; pp++) {
        const int pl = tid + pp * 256;
        float v[16];
#pragma unroll
        for (int c = 0; c < 16; c++)
            v[c] = fmaf(T[c * 516 + pl], sc[c], sh[c]);
        uint32_t wd[8];
#pragma unroll
        for (int j = 0; j < 8; j++)
            wd[wpos8(j)] = pk_bf2(v[2 * j], v[2 * j + 1]);
        uint4* dst = (uint4*)(hnw + (pc + pl) * 128 + b * 8);
        dst[0] = make_uint4(wd[0], wd[1], wd[2], wd[3]);
        dst[1] = make_uint4(wd[4], wd[5], wd[6], wd[7]);
    }
}

// ---------------------------------------------------------------------------
// Kernel 1c: weight convert, merged (validated r14).
// ---------------------------------------------------------------------------
__global__ void wcvt_kernel(const float* __restrict__ Wq,
                            const float* __restrict__ Wk,
                            const float* __restrict__ Wv,
                            const float* __restrict__ Wp) {
    const int z = blockIdx.y;
    int e = blockIdx.x * 256 + threadIdx.x;
    int o = e >> 7, c2 = e & 127;
    if (z < 3) {
        const float* W = (z == 0) ? Wq : (z == 1) ? Wk : Wv;
        uint32_t* wbw = (uint32_t*)g_wb + z * 32768;
        float2 wv = *(const float2*)(W + o * 256 + 2 * c2);
        wbw[o * 128 + (c2 >> 3) * 8 + wpos8(c2 & 7)] = pk_bf2(wv.x, wv.y);
    } else {
        float2 wv = *(const float2*)(Wp + o * 256 + 2 * c2);
        int cbase = (2 * c2) & ~7, cl = (2 * c2) & 7;
        g_wpt[o * 256 + cbase + wpos8(cl)]     = tf32r(wv.x);
        g_wpt[o * 256 + cbase + wpos8(cl + 1)] = tf32r(wv.y);
    }
}

// ---------------------------------------------------------------------------
// Kernel 2: Q/K/V projection, bf16 mma, cp.async double-buffered (validated).
// ---------------------------------------------------------------------------
#define QKV_STG_W (2 * 128 * 40)
#define QKV_SMEM  (2 * QKV_STG_W * 4)

__global__ __launch_bounds__(256, 1) void qkv_mma_kernel(
        const float* __restrict__ bq, const float* __restrict__ bk,
        const float* __restrict__ bv) {
    extern __shared__ uint32_t sbuf[];

    const int tid = threadIdx.x;
    const int w = tid >> 5, lane = tid & 31;
    const int g = lane >> 2, tig = lane & 3;
    const int p0 = blockIdx.x * 128;
    const int o0 = blockIdx.y * 128;
    const int z  = blockIdx.z;
    const float* bias = (z == 0) ? bq : (z == 1) ? bk : bv;

    const uint32_t* hnw = (const uint32_t*)g_hnb;
    const uint32_t* wbw = (const uint32_t*)g_wb + z * 32768;

    const uint32_t sb = smem_u32(sbuf);
    int rr[4], q4[4];
#pragma unroll
    for (int i = 0; i < 4; i++) {
        int e = i * 256 + tid;
        rr[i] = e >> 3; q4[i] = e & 7;
    }

    float acc[16][4] = {};

#pragma unroll
    for (int i = 0; i < 4; i++) {
        cp16(sb + (rr[i] * 40 + q4[i] * 4) * 4,
             hnw + (p0 + rr[i]) * 128 + q4[i] * 4);
        cp16(sb + ((128 * 40) + rr[i] * 40 + q4[i] * 4) * 4,
             wbw + (o0 + rr[i]) * 128 + q4[i] * 4);
    }
    CP_COMMIT();

    for (int ch = 0; ch < 4; ch++) {
        CP_WAIT0();
        __syncthreads();
        if (ch < 3) {
            const uint32_t db = sb + ((ch + 1) & 1) * QKV_STG_W * 4;
#pragma unroll
            for (int i = 0; i < 4; i++) {
                cp16(db + (rr[i] * 40 + q4[i] * 4) * 4,
                     hnw + (p0 + rr[i]) * 128 + (ch + 1) * 32 + q4[i] * 4);
                cp16(db + ((128 * 40) + rr[i] * 40 + q4[i] * 4) * 4,
                     wbw + (o0 + rr[i]) * 128 + (ch + 1) * 32 + q4[i] * 4);
            }
            CP_COMMIT();
        }
        const uint32_t* Aw = sbuf + (ch & 1) * QKV_STG_W;
        const uint32_t* Bw = Aw + 128 * 40;

        uint32_t a[4][4];
#pragma unroll
        for (int ks = 0; ks < 4; ks++) {
            uint2 t0 = *(const uint2*)(Aw + (w * 16 + g)     * 40 + ks * 8 + 2 * tig);
            uint2 t1 = *(const uint2*)(Aw + (w * 16 + g + 8) * 40 + ks * 8 + 2 * tig);
            a[ks][0] = t0.x; a[ks][1] = t1.x; a[ks][2] = t0.y; a[ks][3] = t1.y;
        }
#pragma unroll
        for (int nt = 0; nt < 16; nt++) {
            const uint32_t* bb = Bw + (nt * 8 + g) * 40 + 2 * tig;
#pragma unroll
            for (int ks = 0; ks < 4; ks++) {
                uint2 t = *(const uint2*)(bb + ks * 8);
                mma_bf16(acc[nt], a[ks][0], a[ks][1], a[ks][2], a[ks][3], t.x, t.y);
            }
        }
    }

    if (z < 2) {
        const float s = (z == 0) ? QSCALE2 : 1.f;
        uint32_t* dst = (uint32_t*)((z == 0) ? g_qb : g_kb);
        const int p = p0 + w * 16 + g;
#pragma unroll
        for (int nt = 0; nt < 16; nt++) {
            const int o = o0 + nt * 8 + 2 * tig;
            const float b0 = bias[o], b1 = bias[o + 1];
            const int wi = (o0 >> 4) * 8 + (nt >> 1) * 8 + 2 * tig + (nt & 1);
            dst[p * 128 + wi]       = pk_bf2((acc[nt][0] + b0) * s, (acc[nt][1] + b1) * s);
            dst[(p + 8) * 128 + wi] = pk_bf2((acc[nt][2] + b0) * s, (acc[nt][3] + b1) * s);
        }
    } else {
        __syncthreads();
        __nv_bfloat16* Vs = (__nv_bfloat16*)sbuf;
        const int plA = perm16(w * 16 + g), plB = perm16(w * 16 + g + 8);
#pragma unroll
        for (int nt = 0; nt < 16; nt++) {
            const int ol = nt * 8 + 2 * tig;
            const float b0 = bias[o0 + ol], b1 = bias[o0 + ol + 1];
            Vs[ol * 130 + plA]       = __float2bfloat16(acc[nt][0] + b0);
            Vs[(ol + 1) * 130 + plA] = __float2bfloat16(acc[nt][1] + b1);
            Vs[ol * 130 + plB]       = __float2bfloat16(acc[nt][2] + b0);
            Vs[(ol + 1) * 130 + plB] = __float2bfloat16(acc[nt][3] + b1);
        }
        __syncthreads();
        uint32_t* vtw = (uint32_t*)g_vtb;
        const uint32_t* vsw = (const uint32_t*)Vs;
#pragma unroll
        for (int i = 0; i < 32; i++) {
            int e = i * 256 + tid;
            int r = e >> 6, cc = e & 63;
            vtw[(o0 + r) * 2048 + (p0 >> 1) + cc] = vsw[r * 65 + cc];
        }
    }
}

// ---------------------------------------------------------------------------
// Kernel 3: attention, split-K x4 (load balance), 3-stage cp.async ring,
// one barrier per tile (validated r13/r14 inner loops).
// ---------------------------------------------------------------------------
#define PITCH 40
#define STG_W (2 * 64 * PITCH)
#define KT_PER (64 / NSPLIT)
#define ATTN_SMEM (3 * STG_W * 4)

__global__ __launch_bounds__(256, 2) void attn_mma_kernel() {
    extern __shared__ uint32_t dbuf[];

    const int tid  = threadIdx.x;
    const int w    = tid >> 5, lane = tid & 31;
    const int g    = lane >> 2, tig = lane & 3;
    const int head = blockIdx.y;
    const int q0   = blockIdx.x * 128;
    const int spl  = blockIdx.z;
    const int kt0  = spl * KT_PER;

    const __nv_bfloat16* gq  = g_qb  + head * HD;
    const __nv_bfloat16* gk  = g_kb  + head * HD + kt0 * 64 * C;
    const __nv_bfloat16* gvt = g_vtb + head * HD * N + kt0 * 64;

    uint32_t qa[4][4];
    {
        const int r0 = q0 + w * 16 + g;
#pragma unroll
        for (int ks = 0; ks < 4; ks++) {
            uint2 t0 = *(const uint2*)(gq +  r0      * C + ks * 16 + 4 * tig);
            uint2 t1 = *(const uint2*)(gq + (r0 + 8) * C + ks * 16 + 4 * tig);
            qa[ks][0] = t0.x; qa[ks][1] = t1.x; qa[ks][2] = t0.y; qa[ks][3] = t1.y;
        }
    }

    const uint32_t sb = smem_u32(dbuf);
    int rr[2], cc4[2];
#pragma unroll
    for (int i = 0; i < 2; i++) {
        int e = i * 256 + tid;
        rr[i] = e >> 3; cc4[i] = e & 7;
    }

    float oacc[8][4] = {};
    float l0 = 0.f, l1 = 0.f;

#pragma unroll
    for (int t = 0; t < 2; t++) {
        const uint32_t db = sb + t * STG_W * 4;
        const __nv_bfloat16* ks_src = gk + t * 64 * C;
        const __nv_bfloat16* vs_src = gvt + t * 64;
#pragma unroll
        for (int i = 0; i < 2; i++) {
            cp16(db + (rr[i] * PITCH + cc4[i] * 4) * 4, ks_src + rr[i] * C + cc4[i] * 8);
            cp16(db + (64 * PITCH + rr[i] * PITCH + cc4[i] * 4) * 4,
                 vs_src + rr[i] * N + cc4[i] * 8);
        }
        CP_COMMIT();
    }

    for (int kt = 0; kt < KT_PER; kt++) {
        if (kt + 1 < KT_PER) { CP_WAIT1(); } else { CP_WAIT0(); }
        __syncthreads();

        if (kt + 2 < KT_PER) {
            const uint32_t db = sb + ((kt + 2) % 3) * STG_W * 4;
            const __nv_bfloat16* ks_src = gk + (kt + 2) * 64 * C;
            const __nv_bfloat16* vs_src = gvt + (kt + 2) * 64;
#pragma unroll
            for (int i = 0; i < 2; i++) {
                cp16(db + (rr[i] * PITCH + cc4[i] * 4) * 4,
                     ks_src + rr[i] * C + cc4[i] * 8);
                cp16(db + (64 * PITCH + rr[i] * PITCH + cc4[i] * 4) * 4,
                     vs_src + rr[i] * N + cc4[i] * 8);
            }
            CP_COMMIT();
        }

        const uint32_t* Kc = dbuf + (kt % 3) * STG_W;
        const uint32_t* Vc = Kc + 64 * PITCH;

        float p[8][4];
#pragma unroll
        for (int nt = 0; nt < 8; nt++) {
            float s[4] = {};
            const uint32_t* kb = Kc + (nt * 8 + g) * PITCH + 2 * tig;
#pragma unroll
            for (int ks = 0; ks < 4; ks++) {
                uint2 b = *(const uint2*)(kb + ks * 8);
                mma_bf16(s, qa[ks][0], qa[ks][1], qa[ks][2], qa[ks][3], b.x, b.y);
            }
            p[nt][0] = ex2(s[0]); p[nt][1] = ex2(s[1]);
            p[nt][2] = ex2(s[2]); p[nt][3] = ex2(s[3]);
            l0 += p[nt][0] + p[nt][1];
            l1 += p[nt][2] + p[nt][3];
        }

#pragma unroll
        for (int ks = 0; ks < 4; ks++) {
            const uint32_t pa0 = pk_bf2(p[2 * ks][0],     p[2 * ks][1]);
            const uint32_t pa1 = pk_bf2(p[2 * ks][2],     p[2 * ks][3]);
            const uint32_t pa2 = pk_bf2(p[2 * ks + 1][0], p[2 * ks + 1][1]);
            const uint32_t pa3 = pk_bf2(p[2 * ks + 1][2], p[2 * ks + 1][3]);
            const uint32_t* vb = Vc + g * PITCH + ks * 8 + 2 * tig;
#pragma unroll
            for (int nt = 0; nt < 8; nt++) {
                uint2 b = *(const uint2*)(vb + nt * 8 * PITCH);
                mma_bf16(oacc[nt], pa0, pa1, pa2, pa3, b.x, b.y);
            }
        }
    }

    l0 += __shfl_xor_sync(0xffffffffu, l0, 1);
    l0 += __shfl_xor_sync(0xffffffffu, l0, 2);
    l1 += __shfl_xor_sync(0xffffffffu, l1, 1);
    l1 += __shfl_xor_sync(0xffffffffu, l1, 2);

    const int r0 = q0 + w * 16 + g;
    if (tig == 0) {
        g_pl[(spl * HEADS + head) * N + r0]     = l0;
        g_pl[(spl * HEADS + head) * N + r0 + 8] = l1;
    }
    float* po = g_po + spl * N * C;
#pragma unroll
    for (int nt = 0; nt < 8; nt++) {
        const int col = head * HD + nt * 8 + 2 * tig;
        *(float2*)(po + r0 * C + col)       = make_float2(oacc[nt][0], oacc[nt][1]);
        *(float2*)(po + (r0 + 8) * C + col) = make_float2(oacc[nt][2], oacc[nt][3]);
    }
}

// ---------------------------------------------------------------------------
// Kernel 3c: combine 4 partials (+inline 1/l), normalize, transpose to
// g_ot[p2][perm8 c] (tf32). Block = 64c x 64p2.
// ---------------------------------------------------------------------------
__global__ void combine_t_kernel() {
    __shared__ float T[64 * 65];
    __shared__ float linv_s[64];
    const int tid = threadIdx.x;
    const int p0 = blockIdx.x * 64;
    const int c0 = blockIdx.y * 64;

    const int head = (p0 >> 6) & 3;
    const int pixoff = p0 >> 8;
    if (tid < 64) {
        int pidx = head * N + (c0 + tid) * 16 + pixoff;
        float l = 0.f;
#pragma unroll
        for (int s = 0; s < NSPLIT; s++) l += g_pl[s * HEADS * N + pidx];
        linv_s[tid] = 1.f / l;
    }
    __syncthreads();

#pragma unroll
    for (int i = 0; i < 16; i++) {
        int idx = tid + i * 256;
        int cl = idx >> 6, pl = idx & 63;
        int f = (c0 + cl) * N + p0 + pl;
        float v = 0.f;
#pragma unroll
        for (int s = 0; s < NSPLIT; s++) v += g_po[s * N * C + f];
        T[cl * 65 + pl] = v * linv_s[cl];
    }
    __syncthreads();
#pragma unroll
    for (int i = 0; i < 16; i++) {
        int idx = tid + i * 256;
        int pl = idx >> 6, cl = idx & 63;
        int cperm = c0 + (cl & ~7) + wpos8(cl & 7);
        g_ot[(p0 + pl) * 256 + cperm] = tf32r(T[cl * 65 + pl]);
    }
}

// ---------------------------------------------------------------------------
// Kernel 4: proj via tf32 mma + residual (validated r13/r14).
// ---------------------------------------------------------------------------
__global__ __launch_bounds__(128, 2) void proj_mma_kernel(
        const float* __restrict__ bp,
        const float* __restrict__ x, float* __restrict__ out) {
    __shared__ uint32_t Aw[64 * 40];
    __shared__ uint32_t Bw[128 * 40];

    const int tid = threadIdx.x;
    const int w = tid >> 5, lane = tid & 31;
    const int g = lane >> 2, tig = lane & 3;
    const int p0 = blockIdx.x * 128;
    const int o0 = blockIdx.y * 64;

    const uint32_t* wpt = (const uint32_t*)g_wpt;
    const uint32_t* otw = (const uint32_t*)g_ot;

    float acc[16][4] = {};

    for (int ch = 0; ch < 8; ch++) {
        __syncthreads();
#pragma unroll
        for (int i = 0; i < 4; i++) {
            int e = i * 128 + tid;
            int r = e >> 3, q = e & 7;
            *(uint4*)(Aw + r * 40 + q * 4) =
                *(const uint4*)(wpt + (o0 + r) * 256 + ch * 32 + q * 4);
        }
#pragma unroll
        for (int i = 0; i < 8; i++) {
            int e = i * 128 + tid;
            int r = e >> 3, q = e & 7;
            *(uint4*)(Bw + r * 40 + q * 4) =
                *(const uint4*)(otw + (p0 + r) * 256 + ch * 32 + q * 4);
        }
        __syncthreads();

        uint32_t a[4][4];
#pragma unroll
        for (int ks = 0; ks < 4; ks++) {
            uint2 t0 = *(const uint2*)(Aw + (w * 16 + g)     * 40 + ks * 8 + 2 * tig);
            uint2 t1 = *(const uint2*)(Aw + (w * 16 + g + 8) * 40 + ks * 8 + 2 * tig);
            a[ks][0] = t0.x; a[ks][1] = t1.x; a[ks][2] = t0.y; a[ks][3] = t1.y;
        }
#pragma unroll
        for (int nt = 0; nt < 16; nt++) {
            const uint32_t* bb = Bw + (nt * 8 + g) * 40 + 2 * tig;
#pragma unroll
            for (int ks = 0; ks < 4; ks++) {
                uint2 t = *(const uint2*)(bb + ks * 8);
                mma_tf32(acc[nt], a[ks][0], a[ks][1], a[ks][2], a[ks][3], t.x, t.y);
            }
        }
    }

    const int oo = o0 + w * 16 + g;
    const float b0 = bp[oo], b1 = bp[oo + 8];
#pragma unroll
    for (int nt = 0; nt < 16; nt++) {
        const int pp = p0 + nt * 8 + 2 * tig;
        float2 x0 = *(const float2*)(x + oo * N + pp);
        float2 x1 = *(const float2*)(x + (oo + 8) * N + pp);
        *(float2*)(out + oo * N + pp) =
            make_float2(x0.x + b0 + acc[nt][0], x0.y + b0 + acc[nt][1]);
        *(float2*)(out + (oo + 8) * N + pp) =
            make_float2(x1.x + b1 + acc[nt][2], x1.y + b1 + acc[nt][3]);
    }
}

// ---------------------------------------------------------------------------
extern "C" void kernel_launch(void* const* d_in, const int* in_sizes, int n_in,
                              void* d_out, int out_size) {
    const float* x     = (const float*)d_in[0];
    const float* gamma = (const float*)d_in[1];
    const float* beta  = (const float*)d_in[2];
    const float* Wq    = (const float*)d_in[3];
    const float* bq    = (const float*)d_in[4];
    const float* Wk    = (const float*)d_in[5];
    const float* bk    = (const float*)d_in[6];
    const float* Wv    = (const float*)d_in[7];
    const float* bv    = (const float*)d_in[8];
    const float* Wp    = (const float*)d_in[9];
    const float* bp    = (const float*)d_in[10];
    float* out = (float*)d_out;

    cudaFuncSetAttribute(attn_mma_kernel,
                         cudaFuncAttributeMaxDynamicSharedMemorySize, ATTN_SMEM);
    cudaFuncSetAttribute(qkv_mma_kernel,
                         cudaFuncAttributeMaxDynamicSharedMemorySize, QKV_SMEM);

    dim3 gs(GROUPS, 8);
    gn_stats_kernel<<<gs, 256>>>(x);

    dim3 gw(128, 4);
    wcvt_kernel<<<gw, 256>>>(Wq, Wk, Wv, Wp);   // independent of gn

    dim3 ga(8, 16);
    gn_apply_kernel<<<ga, 256>>>(x, gamma, beta);

    dim3 g2(N / 128, C / 128, 3);
    qkv_mma_kernel<<<g2, 256, QKV_SMEM>>>(bq, bk, bv);

    dim3 g3(N / 128, HEADS, NSPLIT);
    attn_mma_kernel<<<g3, 256, ATTN_SMEM>>>();

    dim3 gc(N / 64, C / 64);
    combine_t_kernel<<<gc, 256>>>();

    dim3 g4(N / 128, C / 64);
    proj_mma_kernel<<<g4, 128>>>(bp, x, out);
}

// round 16
// speedup vs baseline: 1.3419x; 1.0706x over previous
#include <cuda_runtime.h>
#include <cuda_bf16.h>
#include <cstdint>

#define C       256
#define N       4096
#define HEADS   4
#define HD      64
#define GROUPS  32
#define GSIZE   (C / GROUPS)
#define GELEMS  (GSIZE * N)
#define GN_EPS  1e-6f
// 0.125 * log2(e): softmax uses ex2 directly
#define QSCALE2 0.18033688011112042f
#define NSPLIT  4

// bf16 scratch. Channel (or key) index pair-permuted within 16-blocks
// ([0,1,8,9,2,3,10,11,4,5,12,13,6,7,14,15]) so MMA fragments are LDS.64.
__device__ __nv_bfloat16 g_hnb[N * C];     // groupnormed input [p][perm c]
__device__ __nv_bfloat16 g_wb [3 * C * C]; // weights bf16 [o][perm c]
__device__ __nv_bfloat16 g_qb [N * C];
__device__ __nv_bfloat16 g_kb [N * C];
__device__ __nv_bfloat16 g_vtb[C * N];     // V transposed [c][perm p]
__device__ float g_po[NSPLIT * N * C];     // unnormalized O partials
__device__ float g_pl[NSPLIT * HEADS * N]; // l partials [split][head][p]
__device__ float g_ot [N * C];             // proj B operand [p2][perm8 c], tf32
__device__ float g_wpt[C * C];             // Wp tf32 [o][perm8 c]
__device__ float g_gs [GROUPS * 8];        // GN partial sums [group][slice]
__device__ float g_gs2[GROUPS * 8];        // GN partial sumsq

__device__ __forceinline__ int perm16(int i) {
    int b = i & ~15, l = i & 15, j = l >> 1, o = l & 1;
    int p = (j < 4) ? 4 * j : 4 * (j - 4) + 2;
    return b + p + o;
}
__device__ __forceinline__ int wpos8(int j) {
    return (j < 4) ? 2 * j : 2 * (j - 4) + 1;
}
__device__ __forceinline__ uint32_t pk_bf2(float lo, float hi) {
    uint32_t d;
    asm("cvt.rn.bf16x2.f32 %0, %1, %2;" : "=r"(d) : "f"(hi), "f"(lo));
    return d;
}
__device__ __forceinline__ float ex2(float x) {
    float r;
    asm("ex2.approx.f32 %0, %1;" : "=f"(r) : "f"(x));
    return r;
}
__device__ __forceinline__ float tf32r(float f) {
    uint32_t u;
    asm("cvt.rna.tf32.f32 %0, %1;" : "=r"(u) : "f"(f));
    return __uint_as_float(u);
}
__device__ __forceinline__ void mma_bf16(float c[4],
        uint32_t a0, uint32_t a1, uint32_t a2, uint32_t a3,
        uint32_t b0, uint32_t b1) {
    asm volatile("mma.sync.aligned.m16n8k16.row.col.f32.bf16.bf16.f32 "
                 "{%0,%1,%2,%3}, {%4,%5,%6,%7}, {%8,%9}, {%0,%1,%2,%3};"
                 : "+f"(c[0]), "+f"(c[1]), "+f"(c[2]), "+f"(c[3])
                 : "r"(a0), "r"(a1), "r"(a2), "r"(a3), "r"(b0), "r"(b1));
}
__device__ __forceinline__ void mma_tf32(float c[4],
        uint32_t a0, uint32_t a1, uint32_t a2, uint32_t a3,
        uint32_t b0, uint32_t b1) {
    asm volatile("mma.sync.aligned.m16n8k8.row.col.f32.tf32.tf32.f32 "
                 "{%0,%1,%2,%3}, {%4,%5,%6,%7}, {%8,%9}, {%0,%1,%2,%3};"
                 : "+f"(c[0]), "+f"(c[1]), "+f"(c[2]), "+f"(c[3])
                 : "r"(a0), "r"(a1), "r"(a2), "r"(a3), "r"(b0), "r"(b1));
}
__device__ __forceinline__ uint32_t smem_u32(const void* p) {
    uint32_t a;
    asm("{ .reg .u64 t; cvta.to.shared.u64 t, %1; cvt.u32.u64 %0, t; }"
        : "=r"(a) : "l"(p));
    return a;
}
__device__ __forceinline__ void cp16(uint32_t d, const void* s) {
    asm volatile("cp.async.cg.shared.global [%0], [%1], 16;" :: "r"(d), "l"(s));
}
#define CP_COMMIT() asm volatile("cp.async.commit_group;" ::: "memory")
#define CP_WAIT0()  asm volatile("cp.async.wait_group 0;" ::: "memory")
#define CP_WAIT1()  asm volatile("cp.async.wait_group 1;" ::: "memory")

// ---------------------------------------------------------------------------
// Kernel 1a: GN partial stats. grid (32 groups, 8 slices) x 256 (validated).
// ---------------------------------------------------------------------------
__global__ void gn_stats_kernel(const float* __restrict__ x) {
    const int g = blockIdx.x, sl = blockIdx.y, tid = threadIdx.x;
    float s = 0.f, s2 = 0.f;
#pragma unroll
    for (int i = 0; i < 4; i++) {
        int e = i * 256 + tid;
        int c = e >> 7, q = e & 127;
        float4 v = *(const float4*)(x + (g * 8 + c) * N + sl * 512 + q * 4);
        s  += (v.x + v.y) + (v.z + v.w);
        s2 += (v.x * v.x + v.y * v.y) + (v.z * v.z + v.w * v.w);
    }
    __shared__ float r1[256], r2[256];
    r1[tid] = s; r2[tid] = s2;
    __syncthreads();
    for (int st = 128; st > 0; st >>= 1) {
        if (tid < st) { r1[tid] += r1[tid + st]; r2[tid] += r2[tid + st]; }
        __syncthreads();
    }
    if (tid == 0) {
        g_gs [g * 8 + sl] = r1[0];
        g_gs2[g * 8 + sl] = r2[0];
    }
}

// ---------------------------------------------------------------------------
// Kernel 1b: GN apply -> g_hnb bf16 [p][perm16 c] (validated r15).
// ---------------------------------------------------------------------------
__global__ void gn_apply_kernel(const float* __restrict__ x,
                                const float* __restrict__ gamma,
                                const float* __restrict__ beta) {
    const int chunk = blockIdx.x, b = blockIdx.y, tid = threadIdx.x;
    __shared__ float T[16 * 516];
    __shared__ float sc[16], sh[16], murs[4];

    if (tid < 2) {
        float s = 0.f, s2 = 0.f;
#pragma unroll
        for (int i = 0; i < 8; i++) {
            s  += g_gs [(2 * b + tid) * 8 + i];
            s2 += g_gs2[(2 * b + tid) * 8 + i];
        }
        float mu = s * (1.f / GELEMS);
        float var = s2 * (1.f / GELEMS) - mu * mu;
        murs[tid] = mu; murs[2 + tid] = rsqrtf(var + GN_EPS);
    }
    __syncthreads();
    if (tid < 16) {
        int grp = tid >> 3;
        float s = murs[2 + grp] * gamma[16 * b + tid];
        sc[tid] = s;
        sh[tid] = beta[16 * b + tid] - murs[grp] * s;
    }

    const int pc = chunk * 512;
    for (int e = tid; e < 2048; e += 256) {
        int r = e >> 7, c4 = e & 127;
        *(float4*)(T + r * 516 + c4 * 4) =
            *(const float4*)(x + (16 * b + r) * N + pc + c4 * 4);
    }
    __syncthreads();

    uint32_t* hnw = (uint32_t*)g_hnb;
#pragma unroll
    for (int pp = 0; pp < 2; pp++) {
        const int pl = tid + pp * 256;
        float v[16];
#pragma unroll
        for (int c = 0; c < 16; c++)
            v[c] = fmaf(T[c * 516 + pl], sc[c], sh[c]);
        uint32_t wd[8];
#pragma unroll
        for (int j = 0; j < 8; j++)
            wd[wpos8(j)] = pk_bf2(v[2 * j], v[2 * j + 1]);
        uint4* dst = (uint4*)(hnw + (pc + pl) * 128 + b * 8);
        dst[0] = make_uint4(wd[0], wd[1], wd[2], wd[3]);
        dst[1] = make_uint4(wd[4], wd[5], wd[6], wd[7]);
    }
}

// ---------------------------------------------------------------------------
// Kernel 1c: weight convert, merged (validated r14).
// ---------------------------------------------------------------------------
__global__ void wcvt_kernel(const float* __restrict__ Wq,
                            const float* __restrict__ Wk,
                            const float* __restrict__ Wv,
                            const float* __restrict__ Wp) {
    const int z = blockIdx.y;
    int e = blockIdx.x * 256 + threadIdx.x;
    int o = e >> 7, c2 = e & 127;
    if (z < 3) {
        const float* W = (z == 0) ? Wq : (z == 1) ? Wk : Wv;
        uint32_t* wbw = (uint32_t*)g_wb + z * 32768;
        float2 wv = *(const float2*)(W + o * 256 + 2 * c2);
        wbw[o * 128 + (c2 >> 3) * 8 + wpos8(c2 & 7)] = pk_bf2(wv.x, wv.y);
    } else {
        float2 wv = *(const float2*)(Wp + o * 256 + 2 * c2);
        int cbase = (2 * c2) & ~7, cl = (2 * c2) & 7;
        g_wpt[o * 256 + cbase + wpos8(cl)]     = tf32r(wv.x);
        g_wpt[o * 256 + cbase + wpos8(cl + 1)] = tf32r(wv.y);
    }
}

// ---------------------------------------------------------------------------
// Kernel 2: Q/K/V projection, bf16 mma, cp.async, CTA = 64p x 128o,
// 128 threads, 3 CTAs/SM -> grid (64, 2, 3) = 384 CTAs = one wave.
// Stage: A 64x40 words | B 128x40 words = 30KB; 2 stages = 60KB.
// ---------------------------------------------------------------------------
#define QKV_A_W   (64 * 40)
#define QKV_STG_W (QKV_A_W + 128 * 40)   // 7680 words
#define QKV_SMEM  (2 * QKV_STG_W * 4)    // 61440 B

__global__ __launch_bounds__(128, 3) void qkv_mma_kernel(
        const float* __restrict__ bq, const float* __restrict__ bk,
        const float* __restrict__ bv) {
    extern __shared__ uint32_t sbuf[];

    const int tid = threadIdx.x;
    const int w = tid >> 5, lane = tid & 31;
    const int g = lane >> 2, tig = lane & 3;
    const int p0 = blockIdx.x * 64;
    const int o0 = blockIdx.y * 128;
    const int z  = blockIdx.z;
    const float* bias = (z == 0) ? bq : (z == 1) ? bk : bv;

    const uint32_t* hnw = (const uint32_t*)g_hnb;
    const uint32_t* wbw = (const uint32_t*)g_wb + z * 32768;

    const uint32_t sb = smem_u32(sbuf);
    // A: 4 uint4/thread (64 rows), B: 8 uint4/thread (128 rows)
    int ra[4], qa4[4], rb[8], qb4[8];
#pragma unroll
    for (int i = 0; i < 4; i++) {
        int e = i * 128 + tid;
        ra[i] = e >> 3; qa4[i] = e & 7;
    }
#pragma unroll
    for (int i = 0; i < 8; i++) {
        int e = i * 128 + tid;
        rb[i] = e >> 3; qb4[i] = e & 7;
    }

    float acc[16][4] = {};

    // prologue: chunk 0 -> stage 0
#pragma unroll
    for (int i = 0; i < 4; i++)
        cp16(sb + (ra[i] * 40 + qa4[i] * 4) * 4,
             hnw + (p0 + ra[i]) * 128 + qa4[i] * 4);
#pragma unroll
    for (int i = 0; i < 8; i++)
        cp16(sb + (QKV_A_W + rb[i] * 40 + qb4[i] * 4) * 4,
             wbw + (o0 + rb[i]) * 128 + qb4[i] * 4);
    CP_COMMIT();

    for (int ch = 0; ch < 4; ch++) {
        CP_WAIT0();
        __syncthreads();
        if (ch < 3) {
            const uint32_t db = sb + ((ch + 1) & 1) * QKV_STG_W * 4;
#pragma unroll
            for (int i = 0; i < 4; i++)
                cp16(db + (ra[i] * 40 + qa4[i] * 4) * 4,
                     hnw + (p0 + ra[i]) * 128 + (ch + 1) * 32 + qa4[i] * 4);
#pragma unroll
            for (int i = 0; i < 8; i++)
                cp16(db + (QKV_A_W + rb[i] * 40 + qb4[i] * 4) * 4,
                     wbw + (o0 + rb[i]) * 128 + (ch + 1) * 32 + qb4[i] * 4);
            CP_COMMIT();
        }
        const uint32_t* Aw = sbuf + (ch & 1) * QKV_STG_W;
        const uint32_t* Bw = Aw + QKV_A_W;

        uint32_t a[4][4];
#pragma unroll
        for (int ks = 0; ks < 4; ks++) {
            uint2 t0 = *(const uint2*)(Aw + (w * 16 + g)     * 40 + ks * 8 + 2 * tig);
            uint2 t1 = *(const uint2*)(Aw + (w * 16 + g + 8) * 40 + ks * 8 + 2 * tig);
            a[ks][0] = t0.x; a[ks][1] = t1.x; a[ks][2] = t0.y; a[ks][3] = t1.y;
        }
#pragma unroll
        for (int nt = 0; nt < 16; nt++) {
            const uint32_t* bb = Bw + (nt * 8 + g) * 40 + 2 * tig;
#pragma unroll
            for (int ks = 0; ks < 4; ks++) {
                uint2 t = *(const uint2*)(bb + ks * 8);
                mma_bf16(acc[nt], a[ks][0], a[ks][1], a[ks][2], a[ks][3], t.x, t.y);
            }
        }
    }

    if (z < 2) {
        const float s = (z == 0) ? QSCALE2 : 1.f;
        uint32_t* dst = (uint32_t*)((z == 0) ? g_qb : g_kb);
        const int p = p0 + w * 16 + g;
#pragma unroll
        for (int nt = 0; nt < 16; nt++) {
            const int o = o0 + nt * 8 + 2 * tig;
            const float b0 = bias[o], b1 = bias[o + 1];
            const int wi = (o0 >> 4) * 8 + (nt >> 1) * 8 + 2 * tig + (nt & 1);
            dst[p * 128 + wi]       = pk_bf2((acc[nt][0] + b0) * s, (acc[nt][1] + b1) * s);
            dst[(p + 8) * 128 + wi] = pk_bf2((acc[nt][2] + b0) * s, (acc[nt][3] + b1) * s);
        }
    } else {
        __syncthreads();
        __nv_bfloat16* Vs = (__nv_bfloat16*)sbuf;   // [o_local 128][perm p_local 64] pitch 66
        const int plA = perm16(w * 16 + g), plB = perm16(w * 16 + g + 8);
#pragma unroll
        for (int nt = 0; nt < 16; nt++) {
            const int ol = nt * 8 + 2 * tig;
            const float b0 = bias[o0 + ol], b1 = bias[o0 + ol + 1];
            Vs[ol * 66 + plA]       = __float2bfloat16(acc[nt][0] + b0);
            Vs[(ol + 1) * 66 + plA] = __float2bfloat16(acc[nt][1] + b1);
            Vs[ol * 66 + plB]       = __float2bfloat16(acc[nt][2] + b0);
            Vs[(ol + 1) * 66 + plB] = __float2bfloat16(acc[nt][3] + b1);
        }
        __syncthreads();
        uint32_t* vtw = (uint32_t*)g_vtb;
        const uint32_t* vsw = (const uint32_t*)Vs;
#pragma unroll
        for (int i = 0; i < 32; i++) {
            int e = i * 128 + tid;                  // 0..4095 words
            int r = e >> 5, cc = e & 31;
            vtw[(o0 + r) * 2048 + (p0 >> 1) + cc] = vsw[r * 33 + cc];
        }
    }
}

// ---------------------------------------------------------------------------
// Kernel 3: attention, split-K x4, 3-stage cp.async ring (validated r15).
// ---------------------------------------------------------------------------
#define PITCH 40
#define STG_W (2 * 64 * PITCH)
#define KT_PER (64 / NSPLIT)
#define ATTN_SMEM (3 * STG_W * 4)

__global__ __launch_bounds__(256, 2) void attn_mma_kernel() {
    extern __shared__ uint32_t dbuf[];

    const int tid  = threadIdx.x;
    const int w    = tid >> 5, lane = tid & 31;
    const int g    = lane >> 2, tig = lane & 3;
    const int head = blockIdx.y;
    const int q0   = blockIdx.x * 128;
    const int spl  = blockIdx.z;
    const int kt0  = spl * KT_PER;

    const __nv_bfloat16* gq  = g_qb  + head * HD;
    const __nv_bfloat16* gk  = g_kb  + head * HD + kt0 * 64 * C;
    const __nv_bfloat16* gvt = g_vtb + head * HD * N + kt0 * 64;

    uint32_t qa[4][4];
    {
        const int r0 = q0 + w * 16 + g;
#pragma unroll
        for (int ks = 0; ks < 4; ks++) {
            uint2 t0 = *(const uint2*)(gq +  r0      * C + ks * 16 + 4 * tig);
            uint2 t1 = *(const uint2*)(gq + (r0 + 8) * C + ks * 16 + 4 * tig);
            qa[ks][0] = t0.x; qa[ks][1] = t1.x; qa[ks][2] = t0.y; qa[ks][3] = t1.y;
        }
    }

    const uint32_t sb = smem_u32(dbuf);
    int rr[2], cc4[2];
#pragma unroll
    for (int i = 0; i < 2; i++) {
        int e = i * 256 + tid;
        rr[i] = e >> 3; cc4[i] = e & 7;
    }

    float oacc[8][4] = {};
    float l0 = 0.f, l1 = 0.f;

#pragma unroll
    for (int t = 0; t < 2; t++) {
        const uint32_t db = sb + t * STG_W * 4;
        const __nv_bfloat16* ks_src = gk + t * 64 * C;
        const __nv_bfloat16* vs_src = gvt + t * 64;
#pragma unroll
        for (int i = 0; i < 2; i++) {
            cp16(db + (rr[i] * PITCH + cc4[i] * 4) * 4, ks_src + rr[i] * C + cc4[i] * 8);
            cp16(db + (64 * PITCH + rr[i] * PITCH + cc4[i] * 4) * 4,
                 vs_src + rr[i] * N + cc4[i] * 8);
        }
        CP_COMMIT();
    }

    for (int kt = 0; kt < KT_PER; kt++) {
        if (kt + 1 < KT_PER) { CP_WAIT1(); } else { CP_WAIT0(); }
        __syncthreads();

        if (kt + 2 < KT_PER) {
            const uint32_t db = sb + ((kt + 2) % 3) * STG_W * 4;
            const __nv_bfloat16* ks_src = gk + (kt + 2) * 64 * C;
            const __nv_bfloat16* vs_src = gvt + (kt + 2) * 64;
#pragma unroll
            for (int i = 0; i < 2; i++) {
                cp16(db + (rr[i] * PITCH + cc4[i] * 4) * 4,
                     ks_src + rr[i] * C + cc4[i] * 8);
                cp16(db + (64 * PITCH + rr[i] * PITCH + cc4[i] * 4) * 4,
                     vs_src + rr[i] * N + cc4[i] * 8);
            }
            CP_COMMIT();
        }

        const uint32_t* Kc = dbuf + (kt % 3) * STG_W;
        const uint32_t* Vc = Kc + 64 * PITCH;

        float p[8][4];
#pragma unroll
        for (int nt = 0; nt < 8; nt++) {
            float s[4] = {};
            const uint32_t* kb = Kc + (nt * 8 + g) * PITCH + 2 * tig;
#pragma unroll
            for (int ks = 0; ks < 4; ks++) {
                uint2 b = *(const uint2*)(kb + ks * 8);
                mma_bf16(s, qa[ks][0], qa[ks][1], qa[ks][2], qa[ks][3], b.x, b.y);
            }
            p[nt][0] = ex2(s[0]); p[nt][1] = ex2(s[1]);
            p[nt][2] = ex2(s[2]); p[nt][3] = ex2(s[3]);
            l0 += p[nt][0] + p[nt][1];
            l1 += p[nt][2] + p[nt][3];
        }

#pragma unroll
        for (int ks = 0; ks < 4; ks++) {
            const uint32_t pa0 = pk_bf2(p[2 * ks][0],     p[2 * ks][1]);
            const uint32_t pa1 = pk_bf2(p[2 * ks][2],     p[2 * ks][3]);
            const uint32_t pa2 = pk_bf2(p[2 * ks + 1][0], p[2 * ks + 1][1]);
            const uint32_t pa3 = pk_bf2(p[2 * ks + 1][2], p[2 * ks + 1][3]);
            const uint32_t* vb = Vc + g * PITCH + ks * 8 + 2 * tig;
#pragma unroll
            for (int nt = 0; nt < 8; nt++) {
                uint2 b = *(const uint2*)(vb + nt * 8 * PITCH);
                mma_bf16(oacc[nt], pa0, pa1, pa2, pa3, b.x, b.y);
            }
        }
    }

    l0 += __shfl_xor_sync(0xffffffffu, l0, 1);
    l0 += __shfl_xor_sync(0xffffffffu, l0, 2);
    l1 += __shfl_xor_sync(0xffffffffu, l1, 1);
    l1 += __shfl_xor_sync(0xffffffffu, l1, 2);

    const int r0 = q0 + w * 16 + g;
    if (tig == 0) {
        g_pl[(spl * HEADS + head) * N + r0]     = l0;
        g_pl[(spl * HEADS + head) * N + r0 + 8] = l1;
    }
    float* po = g_po + spl * N * C;
#pragma unroll
    for (int nt = 0; nt < 8; nt++) {
        const int col = head * HD + nt * 8 + 2 * tig;
        *(float2*)(po + r0 * C + col)       = make_float2(oacc[nt][0], oacc[nt][1]);
        *(float2*)(po + (r0 + 8) * C + col) = make_float2(oacc[nt][2], oacc[nt][3]);
    }
}

// ---------------------------------------------------------------------------
// Kernel 3c: combine 4 partials (+inline 1/l), normalize, transpose to
// g_ot[p2][perm8 c] (tf32) (validated r15).
// ---------------------------------------------------------------------------
__global__ void combine_t_kernel() {
    __shared__ float T[64 * 65];
    __shared__ float linv_s[64];
    const int tid = threadIdx.x;
    const int p0 = blockIdx.x * 64;
    const int c0 = blockIdx.y * 64;

    const int head = (p0 >> 6) & 3;
    const int pixoff = p0 >> 8;
    if (tid < 64) {
        int pidx = head * N + (c0 + tid) * 16 + pixoff;
        float l = 0.f;
#pragma unroll
        for (int s = 0; s < NSPLIT; s++) l += g_pl[s * HEADS * N + pidx];
        linv_s[tid] = 1.f / l;
    }
    __syncthreads();

#pragma unroll
    for (int i = 0; i < 16; i++) {
        int idx = tid + i * 256;
        int cl = idx >> 6, pl = idx & 63;
        int f = (c0 + cl) * N + p0 + pl;
        float v = 0.f;
#pragma unroll
        for (int s = 0; s < NSPLIT; s++) v += g_po[s * N * C + f];
        T[cl * 65 + pl] = v * linv_s[cl];
    }
    __syncthreads();
#pragma unroll
    for (int i = 0; i < 16; i++) {
        int idx = tid + i * 256;
        int pl = idx >> 6, cl = idx & 63;
        int cperm = c0 + (cl & ~7) + wpos8(cl & 7);
        g_ot[(p0 + pl) * 256 + cperm] = tf32r(T[cl * 65 + pl]);
    }
}

// ---------------------------------------------------------------------------
// Kernel 4: proj via tf32 mma + residual, cp.async double-buffered chunks.
// Stage: A 64x40 | B 128x40 words = 30KB; 2 stages = 60KB dynamic.
// ---------------------------------------------------------------------------
#define PRJ_A_W   (64 * 40)
#define PRJ_STG_W (PRJ_A_W + 128 * 40)
#define PRJ_SMEM  (2 * PRJ_STG_W * 4)

__global__ __launch_bounds__(128, 2) void proj_mma_kernel(
        const float* __restrict__ bp,
        const float* __restrict__ x, float* __restrict__ out) {
    extern __shared__ uint32_t pbuf[];

    const int tid = threadIdx.x;
    const int w = tid >> 5, lane = tid & 31;
    const int g = lane >> 2, tig = lane & 3;
    const int p0 = blockIdx.x * 128;
    const int o0 = blockIdx.y * 64;

    const uint32_t* wpt = (const uint32_t*)g_wpt;
    const uint32_t* otw = (const uint32_t*)g_ot;

    const uint32_t sb = smem_u32(pbuf);
    int ra[4], qa4[4], rb[8], qb4[8];
#pragma unroll
    for (int i = 0; i < 4; i++) {
        int e = i * 128 + tid;
        ra[i] = e >> 3; qa4[i] = e & 7;
    }
#pragma unroll
    for (int i = 0; i < 8; i++) {
        int e = i * 128 + tid;
        rb[i] = e >> 3; qb4[i] = e & 7;
    }

    float acc[16][4] = {};

    // prologue: chunk 0 -> stage 0
#pragma unroll
    for (int i = 0; i < 4; i++)
        cp16(sb + (ra[i] * 40 + qa4[i] * 4) * 4,
             wpt + (o0 + ra[i]) * 256 + qa4[i] * 4);
#pragma unroll
    for (int i = 0; i < 8; i++)
        cp16(sb + (PRJ_A_W + rb[i] * 40 + qb4[i] * 4) * 4,
             otw + (p0 + rb[i]) * 256 + qb4[i] * 4);
    CP_COMMIT();

    for (int ch = 0; ch < 8; ch++) {
        CP_WAIT0();
        __syncthreads();
        if (ch < 7) {
            const uint32_t db = sb + ((ch + 1) & 1) * PRJ_STG_W * 4;
#pragma unroll
            for (int i = 0; i < 4; i++)
                cp16(db + (ra[i] * 40 + qa4[i] * 4) * 4,
                     wpt + (o0 + ra[i]) * 256 + (ch + 1) * 32 + qa4[i] * 4);
#pragma unroll
            for (int i = 0; i < 8; i++)
                cp16(db + (PRJ_A_W + rb[i] * 40 + qb4[i] * 4) * 4,
                     otw + (p0 + rb[i]) * 256 + (ch + 1) * 32 + qb4[i] * 4);
            CP_COMMIT();
        }
        const uint32_t* Aw = pbuf + (ch & 1) * PRJ_STG_W;
        const uint32_t* Bw = Aw + PRJ_A_W;

        uint32_t a[4][4];
#pragma unroll
        for (int ks = 0; ks < 4; ks++) {
            uint2 t0 = *(const uint2*)(Aw + (w * 16 + g)     * 40 + ks * 8 + 2 * tig);
            uint2 t1 = *(const uint2*)(Aw + (w * 16 + g + 8) * 40 + ks * 8 + 2 * tig);
            a[ks][0] = t0.x; a[ks][1] = t1.x; a[ks][2] = t0.y; a[ks][3] = t1.y;
        }
#pragma unroll
        for (int nt = 0; nt < 16; nt++) {
            const uint32_t* bb = Bw + (nt * 8 + g) * 40 + 2 * tig;
#pragma unroll
            for (int ks = 0; ks < 4; ks++) {
                uint2 t = *(const uint2*)(bb + ks * 8);
                mma_tf32(acc[nt], a[ks][0], a[ks][1], a[ks][2], a[ks][3], t.x, t.y);
            }
        }
    }

    const int oo = o0 + w * 16 + g;
    const float b0 = bp[oo], b1 = bp[oo + 8];
#pragma unroll
    for (int nt = 0; nt < 16; nt++) {
        const int pp = p0 + nt * 8 + 2 * tig;
        float2 x0 = *(const float2*)(x + oo * N + pp);
        float2 x1 = *(const float2*)(x + (oo + 8) * N + pp);
        *(float2*)(out + oo * N + pp) =
            make_float2(x0.x + b0 + acc[nt][0], x0.y + b0 + acc[nt][1]);
        *(float2*)(out + (oo + 8) * N + pp) =
            make_float2(x1.x + b1 + acc[nt][2], x1.y + b1 + acc[nt][3]);
    }
}

// ---------------------------------------------------------------------------
extern "C" void kernel_launch(void* const* d_in, const int* in_sizes, int n_in,
                              void* d_out, int out_size) {
    const float* x     = (const float*)d_in[0];
    const float* gamma = (const float*)d_in[1];
    const float* beta  = (const float*)d_in[2];
    const float* Wq    = (const float*)d_in[3];
    const float* bq    = (const float*)d_in[4];
    const float* Wk    = (const float*)d_in[5];
    const float* bk    = (const float*)d_in[6];
    const float* Wv    = (const float*)d_in[7];
    const float* bv    = (const float*)d_in[8];
    const float* Wp    = (const float*)d_in[9];
    const float* bp    = (const float*)d_in[10];
    float* out = (float*)d_out;

    cudaFuncSetAttribute(attn_mma_kernel,
                         cudaFuncAttributeMaxDynamicSharedMemorySize, ATTN_SMEM);
    cudaFuncSetAttribute(qkv_mma_kernel,
                         cudaFuncAttributeMaxDynamicSharedMemorySize, QKV_SMEM);
    cudaFuncSetAttribute(proj_mma_kernel,
                         cudaFuncAttributeMaxDynamicSharedMemorySize, PRJ_SMEM);

    dim3 gs(GROUPS, 8);
    gn_stats_kernel<<<gs, 256>>>(x);

    dim3 gw(128, 4);
    wcvt_kernel<<<gw, 256>>>(Wq, Wk, Wv, Wp);   // independent of gn

    dim3 ga(8, 16);
    gn_apply_kernel<<<ga, 256>>>(x, gamma, beta);

    dim3 g2(N / 64, C / 128, 3);
    qkv_mma_kernel<<<g2, 128, QKV_SMEM>>>(bq, bk, bv);

    dim3 g3(N / 128, HEADS, NSPLIT);
    attn_mma_kernel<<<g3, 256, ATTN_SMEM>>>();

    dim3 gc(N / 64, C / 64);
    combine_t_kernel<<<gc, 256>>>();

    dim3 g4(N / 128, C / 64);
    proj_mma_kernel<<<g4, 128, PRJ_SMEM>>>(bp, x, out);
}